// round 1
// baseline (speedup 1.0000x reference)
#include <cuda_runtime.h>
#include <math.h>

#define BB    16
#define NN    2048
#define DD    64
#define NP    512
#define NS    32
#define SCC   67
#define CH_IN 134
#define KS    (NS*NP)      /* 16384 */
#define EPSBN 1e-5f
#define R2    0.04f

#define OUT_XYZ   0
#define OUT_PTS   (BB*3*NP)                 /* 24576 */
#define OUT_LOSS  (OUT_PTS + BB*256*NP)     /* 2121728 */
#define OUT_UNIQ  (OUT_LOSS + 1)

// ---------------- scratch (static device globals; no allocs) ----------------
__device__ float g_agg [BB*NN*SCC];          // (B,N,67)  [pts(64) | xyz(3)]
__device__ float g_xn  [BB*NN];
__device__ int   g_idx [BB*NN*NS];
__device__ float g_h1  [BB*SCC*NN];          // (B,67,N)
__device__ float g_h2  [BB*NP*NN];           // (B,512,N) -> select after softmax
__device__ float g_norm[BB*NP];
__device__ float g_losspart[BB*64];
__device__ int   g_amax[NP];
__device__ float g_samp[BB*NP*SCC];          // (B,512,67) sel@agg
__device__ float g_gp  [(size_t)BB*NN*(NS*DD)];   // 256MB
__device__ float g_gx  [BB*NN*(NS*3)];
__device__ float g_sgp [BB*NP*(NS*DD)];
__device__ float g_sgx [BB*NP*(NS*3)];
__device__ float g_edge[(size_t)BB*CH_IN*KS];     // 140MB
__device__ float g_c0  [(size_t)BB*128*KS];
__device__ float g_c1  [(size_t)BB*128*KS];
__device__ float g_c2  [(size_t)BB*256*KS];       // 268MB
__device__ float g_bnm [512];
__device__ float g_bnr [512];

// ---------------- prep: transpose into agg, compute xn ----------------
__global__ void k_prep(const float* __restrict__ xyz, const float* __restrict__ pts) {
    int i = blockIdx.x * blockDim.x + threadIdx.x;  // over B*N
    if (i >= BB * NN) return;
    int b = i / NN, n = i % NN;
    float* arow = g_agg + (size_t)i * SCC;
    const float* p = pts + (size_t)b * DD * NN + n;
#pragma unroll 8
    for (int d = 0; d < DD; d++) arow[d] = p[(size_t)d * NN];
    const float* x = xyz + (size_t)b * 3 * NN + n;
    float a = x[0], c = x[NN], e = x[2 * NN];
    arow[64] = a; arow[65] = c; arow[66] = e;
    g_xn[i] = fmaf(e, e, fmaf(c, c, a * a));
}

// ---------------- ball query: first NS in-range indices, pad with first ----------------
__global__ void k_ballquery() {
    __shared__ float sx[NN], sy[NN], sz[NN], sn[NN];
    int b = blockIdx.y;
    int t = threadIdx.x;
    for (int j = t; j < NN; j += blockDim.x) {
        const float* a = g_agg + ((size_t)b * NN + j) * SCC;
        sx[j] = a[64]; sy[j] = a[65]; sz[j] = a[66];
        sn[j] = g_xn[b * NN + j];
    }
    __syncthreads();
    int n = blockIdx.x * blockDim.x + t;
    float px = sx[n], py = sy[n], pz = sz[n], pn = sn[n];
    int base = (b * NN + n) * NS;
    int cnt = 0, first = 0;
    for (int m = 0; m < NN && cnt < NS; m++) {
        float dot = fmaf(px, sx[m], fmaf(py, sy[m], pz * sz[m]));
        float d = pn + sn[m] - 2.0f * dot;
        if (!(d > R2)) {
            if (cnt == 0) first = m;
            g_idx[base + cnt] = m;
            cnt++;
        }
    }
    for (int j = cnt; j < NS; j++) g_idx[base + j] = first;
}

// ---------------- h1 = w1 @ agg  -> (B,67,N) ----------------
__global__ void k_h1(const float* __restrict__ w1) {
    __shared__ float w[SCC];
    int o = blockIdx.y, b = blockIdx.z;
    if (threadIdx.x < SCC) w[threadIdx.x] = w1[o * SCC + threadIdx.x];
    __syncthreads();
    int n = blockIdx.x * blockDim.x + threadIdx.x;
    const float* arow = g_agg + ((size_t)(b * NN + n)) * SCC;
    float s = 0.f;
#pragma unroll 1
    for (int c = 0; c < SCC; c++) s = fmaf(w[c], arow[c], s);
    g_h1[((size_t)b * SCC + o) * NN + n] = s;
}

// ---------------- BN stats over (b, spatial) per channel ----------------
__global__ void k_bnstats(const float* __restrict__ x, int C, int S) {
    int c = blockIdx.x, t = threadIdx.x;
    float s = 0.f, sq = 0.f;
    for (int b = 0; b < BB; b++) {
        const float* p = x + ((size_t)b * C + c) * S;
        for (int j = t; j < S; j += 256) { float v = p[j]; s += v; sq = fmaf(v, v, sq); }
    }
    __shared__ float rs[256], rq[256];
    rs[t] = s; rq[t] = sq; __syncthreads();
    for (int o = 128; o > 0; o >>= 1) {
        if (t < o) { rs[t] += rs[t + o]; rq[t] += rq[t + o]; }
        __syncthreads();
    }
    if (t == 0) {
        float cnt = (float)BB * (float)S;
        float m = rs[0] / cnt;
        float v = rq[0] / cnt - m * m;
        g_bnm[c] = m;
        g_bnr[c] = rsqrtf(fmaxf(v, 0.f) + EPSBN);
    }
}

__global__ void k_bnapply(float* __restrict__ x, const float* __restrict__ g,
                          const float* __restrict__ bt, int C, int S, int leaky) {
    long long i = (long long)blockIdx.x * blockDim.x + threadIdx.x;
    long long tot = (long long)BB * C * S;
    if (i >= tot) return;
    int c = (int)((i / S) % C);
    float v = (x[i] - g_bnm[c]) * g_bnr[c] * g[c] + bt[c];
    if (leaky) v = v > 0.f ? v : 0.2f * v;
    x[i] = v;
}

// ---------------- generic batched SGEMM: C = A(MxK) @ B(KxN), all row-major ----------------
__global__ __launch_bounds__(256) void k_sgemm(
    const float* __restrict__ A, const float* __restrict__ Bm, float* __restrict__ C,
    int M, int N, int K, size_t sA, size_t sB, size_t sC)
{
    const float* Ab = A + blockIdx.z * sA;
    const float* Bb = Bm + blockIdx.z * sB;
    float* Cb = C + blockIdx.z * sC;
    __shared__ float As[8][128];
    __shared__ float Bs[8][128];
    int t = threadIdx.x;
    int tx = t & 15, ty = t >> 4;
    int row0 = blockIdx.y * 128, col0 = blockIdx.x * 128;
    float acc[8][8];
#pragma unroll
    for (int i = 0; i < 8; i++)
#pragma unroll
        for (int j = 0; j < 8; j++) acc[i][j] = 0.f;

    for (int k0 = 0; k0 < K; k0 += 8) {
#pragma unroll
        for (int i = 0; i < 4; i++) {
            int idx = t + i * 256;
            int m = idx >> 3, k = idx & 7;
            float va = 0.f;
            if (row0 + m < M && k0 + k < K) va = Ab[(size_t)(row0 + m) * K + k0 + k];
            As[k][m] = va;
            int k2 = idx >> 7, n = idx & 127;
            float vb = 0.f;
            if (k0 + k2 < K && col0 + n < N) vb = Bb[(size_t)(k0 + k2) * N + col0 + n];
            Bs[k2][n] = vb;
        }
        __syncthreads();
#pragma unroll
        for (int kk = 0; kk < 8; kk++) {
            float a[8], bv[8];
#pragma unroll
            for (int i = 0; i < 8; i++) a[i] = As[kk][ty * 8 + i];
#pragma unroll
            for (int j = 0; j < 8; j++) bv[j] = Bs[kk][tx * 8 + j];
#pragma unroll
            for (int i = 0; i < 8; i++)
#pragma unroll
                for (int j = 0; j < 8; j++)
                    acc[i][j] = fmaf(a[i], bv[j], acc[i][j]);
        }
        __syncthreads();
    }
#pragma unroll
    for (int i = 0; i < 8; i++) {
        int r = row0 + ty * 8 + i;
        if (r >= M) continue;
#pragma unroll
        for (int j = 0; j < 8; j++) {
            int cc = col0 + tx * 8 + j;
            if (cc < N) Cb[(size_t)r * N + cc] = acc[i][j];
        }
    }
}

// ---------------- softmax over N per (b,s); also row norm ----------------
__global__ void k_softmax() {
    int row = blockIdx.x;               // b*NP + s
    float* x = g_h2 + (size_t)row * NN;
    int t = threadIdx.x;
    __shared__ float rs[256], rq[256];
    float m = -1e30f;
    for (int j = t; j < NN; j += 256) m = fmaxf(m, x[j]);
    rs[t] = m; __syncthreads();
    for (int o = 128; o > 0; o >>= 1) { if (t < o) rs[t] = fmaxf(rs[t], rs[t + o]); __syncthreads(); }
    m = rs[0]; __syncthreads();
    float s = 0.f, sq = 0.f;
    for (int j = t; j < NN; j += 256) {
        float e = expf(x[j] - m);
        x[j] = e;
        s += e; sq = fmaf(e, e, sq);
    }
    rs[t] = s; rq[t] = sq; __syncthreads();
    for (int o = 128; o > 0; o >>= 1) { if (t < o) { rs[t] += rs[t + o]; rq[t] += rq[t + o]; } __syncthreads(); }
    s = rs[0]; sq = rq[0];
    float inv = 1.f / s;
    for (int j = t; j < NN; j += 256) x[j] *= inv;
    if (t == 0) g_norm[row] = sqrtf(sq) * inv;
}

// ---------------- argmax of batch-0 rows; unique count ----------------
__global__ void k_argmax() {
    int sidx = blockIdx.x;
    const float* x = g_h2 + (size_t)sidx * NN;   // batch 0
    int t = threadIdx.x;
    float bv = -1e30f; int bi = NN;
    for (int j = t; j < NN; j += 256) { float v = x[j]; if (v > bv) { bv = v; bi = j; } }
    __shared__ float rv[256]; __shared__ int ri[256];
    rv[t] = bv; ri[t] = bi; __syncthreads();
    for (int o = 128; o > 0; o >>= 1) {
        if (t < o) {
            if (rv[t + o] > rv[t] || (rv[t + o] == rv[t] && ri[t + o] < ri[t])) {
                rv[t] = rv[t + o]; ri[t] = ri[t + o];
            }
        }
        __syncthreads();
    }
    if (t == 0) g_amax[sidx] = ri[0];
}

__global__ void k_unique(float* __restrict__ out, int out_size) {
    __shared__ int fl[NN];
    __shared__ int rc[256];
    int t = threadIdx.x;
    for (int j = t; j < NN; j += 256) fl[j] = 0;
    __syncthreads();
    for (int s = t; s < NP; s += 256) fl[g_amax[s]] = 1;
    __syncthreads();
    int c = 0;
    for (int j = t; j < NN; j += 256) c += fl[j];
    rc[t] = c; __syncthreads();
    for (int o = 128; o > 0; o >>= 1) { if (t < o) rc[t] += rc[t + o]; __syncthreads(); }
    if (t == 0 && OUT_UNIQ < out_size) out[OUT_UNIQ] = (float)rc[0];
}

// ---------------- inner = sel@sel^T tile + fused cos-loss partials ----------------
__global__ __launch_bounds__(256) void k_inner_loss() {
    int b = blockIdx.z;
    const float* S = g_h2 + (size_t)b * NP * NN;
    __shared__ float As[16][64];
    __shared__ float Bs[16][64];
    __shared__ float red[256];
    int t = threadIdx.x;
    int tx = t & 15, ty = t >> 4;
    int row0 = blockIdx.y * 64, col0 = blockIdx.x * 64;
    float acc[4][4];
#pragma unroll
    for (int i = 0; i < 4; i++)
#pragma unroll
        for (int j = 0; j < 4; j++) acc[i][j] = 0.f;

    for (int k0 = 0; k0 < NN; k0 += 16) {
#pragma unroll
        for (int i = 0; i < 4; i++) {
            int idx = t * 4 + i;
            int m = idx >> 4, k = idx & 15;
            As[k][m] = S[(size_t)(row0 + m) * NN + k0 + k];
            Bs[k][m] = S[(size_t)(col0 + m) * NN + k0 + k];
        }
        __syncthreads();
#pragma unroll
        for (int kk = 0; kk < 16; kk++) {
            float a[4], bv[4];
#pragma unroll
            for (int i = 0; i < 4; i++) a[i] = As[kk][ty * 4 + i];
#pragma unroll
            for (int j = 0; j < 4; j++) bv[j] = Bs[kk][tx * 4 + j];
#pragma unroll
            for (int i = 0; i < 4; i++)
#pragma unroll
                for (int j = 0; j < 4; j++)
                    acc[i][j] = fmaf(a[i], bv[j], acc[i][j]);
        }
        __syncthreads();
    }
    float part = 0.f;
#pragma unroll
    for (int i = 0; i < 4; i++) {
        int ss = row0 + ty * 4 + i;
        float ns = g_norm[b * NP + ss];
#pragma unroll
        for (int j = 0; j < 4; j++) {
            int tt = col0 + tx * 4 + j;
            float v = acc[i][j] / (ns * g_norm[b * NP + tt] + 1e-10f);
            if (ss != tt) part = fmaf(v, v, part);
        }
    }
    red[t] = part; __syncthreads();
    for (int o = 128; o > 0; o >>= 1) { if (t < o) red[t] += red[t + o]; __syncthreads(); }
    if (t == 0) g_losspart[b * 64 + blockIdx.y * 8 + blockIdx.x] = red[0];
}

__global__ void k_lossfin(float* __restrict__ out, int out_size) {
    if (threadIdx.x == 0 && OUT_LOSS < out_size) {
        float acc = 0.f;
        for (int b = 0; b < BB; b++) {
            float s = 0.f;
            for (int i = 0; i < 64; i++) s += g_losspart[b * 64 + i];
            acc += sqrtf(s);
        }
        out[OUT_LOSS] = acc / (float)BB;
    }
}

// ---------------- gather grouped points/xyz -> gp (B,N,32*64), gx (B,N,32*3) ----------------
__global__ void k_gather() {
    int i = blockIdx.x * blockDim.x + threadIdx.x;   // B*N*NS
    if (i >= BB * NN * NS) return;
    int k = i % NS; int n = (i / NS) % NN; int b = i / (NS * NN);
    int id = g_idx[i];
    const float* src = g_agg + ((size_t)b * NN + id) * SCC;
    float* dp = g_gp + ((size_t)(b * NN + n)) * (NS * DD) + k * DD;
#pragma unroll 8
    for (int d = 0; d < DD; d++) dp[d] = src[d];
    float* dx = g_gx + ((size_t)(b * NN + n)) * (NS * 3) + k * 3;
    dx[0] = src[64]; dx[1] = src[65]; dx[2] = src[66];
}

// ---------------- edge build: (B,134,32,512) ----------------
__global__ void k_edge() {
    long long i = (long long)blockIdx.x * blockDim.x + threadIdx.x;
    long long tot = (long long)BB * CH_IN * KS;
    if (i >= tot) return;
    int s = (int)(i % NP);
    int k = (int)((i / NP) % NS);
    int c = (int)((i / KS) % CH_IN);
    int b = (int)(i / ((long long)CH_IN * KS));
    const float* samp = g_samp + ((size_t)b * NP + s) * SCC;
    float v;
    if (c < 64) {
        v = samp[c];
    } else if (c < 128) {
        int d = c - 64;
        v = g_sgp[((size_t)b * NP + s) * (NS * DD) + k * DD + d] - samp[d];
    } else if (c < 131) {
        v = samp[64 + (c - 128)];
    } else {
        int cc = c - 131;
        v = g_sgx[((size_t)b * NP + s) * (NS * 3) + k * 3 + cc] - samp[64 + cc];
    }
    g_edge[i] = v;
}

// ---------------- maxpool over NS + write new_points ----------------
__global__ void k_maxpool(float* __restrict__ out, int out_size) {
    int i = blockIdx.x * blockDim.x + threadIdx.x;   // B*256*NP
    if (i >= BB * 256 * NP) return;
    int s = i % NP; int o = (i / NP) % 256; int b = i / (256 * NP);
    const float* p = g_c2 + ((size_t)b * 256 + o) * KS + s;
    float m = -1e30f;
#pragma unroll
    for (int k = 0; k < NS; k++) m = fmaxf(m, p[k * NP]);
    int oi = OUT_PTS + i;
    if (oi < out_size) out[oi] = m;
}

__global__ void k_wxyz(float* __restrict__ out, int out_size) {
    int i = blockIdx.x * blockDim.x + threadIdx.x;   // B*3*NP
    if (i >= BB * 3 * NP) return;
    int s = i % NP; int c = (i / NP) % 3; int b = i / (3 * NP);
    if (i < out_size) out[i] = g_samp[((size_t)b * NP + s) * SCC + 64 + c];
}

// ---------------- launch ----------------
extern "C" void kernel_launch(void* const* d_in, const int* in_sizes, int n_in,
                              void* d_out, int out_size) {
    const float* xyz   = (const float*)d_in[0];
    const float* pts   = (const float*)d_in[1];
    const float* w1_w  = (const float*)d_in[2];
    const float* bn1_g = (const float*)d_in[4];
    const float* bn1_b = (const float*)d_in[5];
    const float* w2_w  = (const float*)d_in[6];
    const float* bn2_g = (const float*)d_in[8];
    const float* bn2_b = (const float*)d_in[9];
    const float* c0w   = (const float*)d_in[10];
    const float* bg0   = (const float*)d_in[12];
    const float* bb0   = (const float*)d_in[13];
    const float* c1w   = (const float*)d_in[14];
    const float* bg1   = (const float*)d_in[16];
    const float* bb1   = (const float*)d_in[17];
    const float* c2w   = (const float*)d_in[18];
    const float* bg2   = (const float*)d_in[20];
    const float* bb2   = (const float*)d_in[21];
    float* out = (float*)d_out;

    float *p_agg, *p_h1, *p_h2, *p_samp, *p_gp, *p_gx, *p_sgp, *p_sgx, *p_edge, *p_c0, *p_c1, *p_c2;
    cudaGetSymbolAddress((void**)&p_agg,  g_agg);
    cudaGetSymbolAddress((void**)&p_h1,   g_h1);
    cudaGetSymbolAddress((void**)&p_h2,   g_h2);
    cudaGetSymbolAddress((void**)&p_samp, g_samp);
    cudaGetSymbolAddress((void**)&p_gp,   g_gp);
    cudaGetSymbolAddress((void**)&p_gx,   g_gx);
    cudaGetSymbolAddress((void**)&p_sgp,  g_sgp);
    cudaGetSymbolAddress((void**)&p_sgx,  g_sgx);
    cudaGetSymbolAddress((void**)&p_edge, g_edge);
    cudaGetSymbolAddress((void**)&p_c0,   g_c0);
    cudaGetSymbolAddress((void**)&p_c1,   g_c1);
    cudaGetSymbolAddress((void**)&p_c2,   g_c2);

    k_prep<<<(BB * NN + 255) / 256, 256>>>(xyz, pts);
    k_ballquery<<<dim3(NN / 256, BB), 256>>>();
    k_h1<<<dim3(NN / 256, SCC, BB), 256>>>(w1_w);
    k_bnstats<<<SCC, 256>>>(p_h1, SCC, NN);
    k_bnapply<<<(BB * SCC * NN + 255) / 256, 256>>>(p_h1, bn1_g, bn1_b, SCC, NN, 0);
    // h2 = w2 @ h1
    k_sgemm<<<dim3(16, 4, BB), 256>>>(w2_w, p_h1, p_h2, NP, NN, SCC,
                                      0, (size_t)SCC * NN, (size_t)NP * NN);
    k_bnstats<<<NP, 256>>>(p_h2, NP, NN);
    k_bnapply<<<(BB * NP * NN + 255) / 256, 256>>>(p_h2, bn2_g, bn2_b, NP, NN, 0);
    k_softmax<<<BB * NP, 256>>>();
    k_argmax<<<NP, 256>>>();
    k_unique<<<1, 256>>>(out, out_size);
    k_inner_loss<<<dim3(8, 8, BB), 256>>>();
    k_lossfin<<<1, 1>>>(out, out_size);
    // samp = sel @ agg  (512 x 67)
    k_sgemm<<<dim3(1, 4, BB), 256>>>(p_h2, p_agg, p_samp, NP, SCC, NN,
                                     (size_t)NP * NN, (size_t)NN * SCC, (size_t)NP * SCC);
    k_gather<<<(BB * NN * NS + 255) / 256, 256>>>();
    // sgp = sel @ gp   (512 x 2048, K=2048)  -- dominant GEMM
    k_sgemm<<<dim3(16, 4, BB), 256>>>(p_h2, p_gp, p_sgp, NP, NS * DD, NN,
                                      (size_t)NP * NN, (size_t)NN * NS * DD, (size_t)NP * NS * DD);
    // sgx = sel @ gx   (512 x 96)
    k_sgemm<<<dim3(1, 4, BB), 256>>>(p_h2, p_gx, p_sgx, NP, NS * 3, NN,
                                     (size_t)NP * NN, (size_t)NN * NS * 3, (size_t)NP * NS * 3);
    k_edge<<<(int)(((long long)BB * CH_IN * KS + 255) / 256), 256>>>();
    // conv0
    k_sgemm<<<dim3(KS / 128, 1, BB), 256>>>(c0w, p_edge, p_c0, 128, KS, CH_IN,
                                            0, (size_t)CH_IN * KS, (size_t)128 * KS);
    k_bnstats<<<128, 256>>>(p_c0, 128, KS);
    k_bnapply<<<(int)(((long long)BB * 128 * KS + 255) / 256), 256>>>(p_c0, bg0, bb0, 128, KS, 1);
    // conv1
    k_sgemm<<<dim3(KS / 128, 1, BB), 256>>>(c1w, p_c0, p_c1, 128, KS, 128,
                                            0, (size_t)128 * KS, (size_t)128 * KS);
    k_bnstats<<<128, 256>>>(p_c1, 128, KS);
    k_bnapply<<<(int)(((long long)BB * 128 * KS + 255) / 256), 256>>>(p_c1, bg1, bb1, 128, KS, 1);
    // conv2
    k_sgemm<<<dim3(KS / 128, 2, BB), 256>>>(c2w, p_c1, p_c2, 256, KS, 128,
                                            0, (size_t)128 * KS, (size_t)256 * KS);
    k_bnstats<<<256, 256>>>(p_c2, 256, KS);
    k_bnapply<<<(int)(((long long)BB * 256 * KS + 255) / 256), 256>>>(p_c2, bg2, bb2, 256, KS, 1);
    k_maxpool<<<(BB * 256 * NP + 255) / 256, 256>>>(out, out_size);
    k_wxyz<<<(BB * 3 * NP + 255) / 256, 256>>>(out, out_size);
}

// round 2
// speedup vs baseline: 1.7144x; 1.7144x over previous
#include <cuda_runtime.h>
#include <math.h>

#define BB    16
#define NN    2048
#define DD    64
#define NP    512
#define NS    32
#define SCC   67
#define CH_IN 134
#define CH_P  144
#define KS    (NS*NP)      /* 16384 */
#define EPSBN 1e-5f
#define R2    0.04f

#define OUT_PTS   (BB*3*NP)
#define OUT_LOSS  (OUT_PTS + BB*256*NP)
#define OUT_UNIQ  (OUT_LOSS + 1)

// ---------------- scratch ----------------
__device__ float g_agg [BB*NN*SCC];
__device__ float g_xn  [BB*NN];
__device__ int   g_idx [BB*NN*NS];
__device__ float g_h1  [BB*SCC*NN];
__device__ float g_h2  [BB*NP*NN];           // raw h2, then select in place
__device__ float g_norm[BB*NP];
__device__ float g_losspart[BB];
__device__ int   g_amax[NP];
__device__ float g_samp[BB*NP*SCC];
__device__ float g_gp  [(size_t)BB*NN*(NS*DD)];
__device__ float g_gx  [BB*NN*(NS*3)];
__device__ float g_sgp [BB*NP*(NS*DD)];
__device__ float g_sgx [BB*NP*(NS*3)];
__device__ float g_inner[(size_t)BB*NP*NP];
__device__ float g_edge[(size_t)BB*CH_P*KS];
__device__ float g_w0p [128*CH_P];
__device__ float g_c0  [(size_t)BB*128*KS];
__device__ float g_c1  [(size_t)BB*128*KS];
__device__ float g_c2  [(size_t)BB*256*KS];
__device__ float g_bnm [512];
__device__ float g_bnr [512];

// ---------------- prep ----------------
__global__ void k_prep(const float* __restrict__ xyz, const float* __restrict__ pts) {
    int i = blockIdx.x * blockDim.x + threadIdx.x;
    if (i >= BB * NN) return;
    int b = i / NN, n = i % NN;
    float* arow = g_agg + (size_t)i * SCC;
    const float* p = pts + (size_t)b * DD * NN + n;
#pragma unroll 8
    for (int d = 0; d < DD; d++) arow[d] = p[(size_t)d * NN];
    const float* x = xyz + (size_t)b * 3 * NN + n;
    float a = x[0], c = x[NN], e = x[2 * NN];
    arow[64] = a; arow[65] = c; arow[66] = e;
    g_xn[i] = fmaf(e, e, fmaf(c, c, a * a));
}

// ---------------- ball query ----------------
__global__ void k_ballquery() {
    __shared__ float sx[NN], sy[NN], sz[NN], sn[NN];
    int b = blockIdx.y;
    int t = threadIdx.x;
    for (int j = t; j < NN; j += blockDim.x) {
        const float* a = g_agg + ((size_t)b * NN + j) * SCC;
        sx[j] = a[64]; sy[j] = a[65]; sz[j] = a[66];
        sn[j] = g_xn[b * NN + j];
    }
    __syncthreads();
    int n = blockIdx.x * blockDim.x + t;
    float px = sx[n], py = sy[n], pz = sz[n], pn = sn[n];
    int base = (b * NN + n) * NS;
    int cnt = 0, first = 0;
    for (int m = 0; m < NN && cnt < NS; m++) {
        float dot = fmaf(px, sx[m], fmaf(py, sy[m], pz * sz[m]));
        float d = pn + sn[m] - 2.0f * dot;
        if (!(d > R2)) {
            if (cnt == 0) first = m;
            g_idx[base + cnt] = m;
            cnt++;
        }
    }
    for (int j = cnt; j < NS; j++) g_idx[base + j] = first;
}

// ---------------- h1 = w1 @ agg (raw, fp32) ----------------
__global__ void k_h1(const float* __restrict__ w1) {
    __shared__ float w[SCC];
    int o = blockIdx.y, b = blockIdx.z;
    if (threadIdx.x < SCC) w[threadIdx.x] = w1[o * SCC + threadIdx.x];
    __syncthreads();
    int n = blockIdx.x * blockDim.x + threadIdx.x;
    const float* arow = g_agg + ((size_t)(b * NN + n)) * SCC;
    float s = 0.f;
#pragma unroll 1
    for (int c = 0; c < SCC; c++) s = fmaf(w[c], arow[c], s);
    g_h1[((size_t)b * SCC + o) * NN + n] = s;
}

// ---------------- BN stats ----------------
__global__ void k_bnstats(const float* __restrict__ x, int C, int S) {
    int c = blockIdx.x, t = threadIdx.x;
    float s = 0.f, sq = 0.f;
    for (int b = 0; b < BB; b++) {
        const float* p = x + ((size_t)b * C + c) * S;
        for (int j = t; j < S; j += 256) { float v = p[j]; s += v; sq = fmaf(v, v, sq); }
    }
    __shared__ float rs[256], rq[256];
    rs[t] = s; rq[t] = sq; __syncthreads();
    for (int o = 128; o > 0; o >>= 1) {
        if (t < o) { rs[t] += rs[t + o]; rq[t] += rq[t + o]; }
        __syncthreads();
    }
    if (t == 0) {
        float cnt = (float)BB * (float)S;
        float m = rs[0] / cnt;
        float v = rq[0] / cnt - m * m;
        g_bnm[c] = m;
        g_bnr[c] = rsqrtf(fmaxf(v, 0.f) + EPSBN);
    }
}

// ---------------- generic fp32 SGEMM (small/odd shapes), optional BN on B ----------------
__global__ __launch_bounds__(256) void k_sgemm(
    const float* __restrict__ A, const float* __restrict__ Bm, float* __restrict__ C,
    int M, int N, int K, size_t sA, size_t sB, size_t sC,
    const float* __restrict__ bnm, const float* __restrict__ bnr,
    const float* __restrict__ bng, const float* __restrict__ bnb)
{
    const float* Ab = A + blockIdx.z * sA;
    const float* Bb = Bm + blockIdx.z * sB;
    float* Cb = C + blockIdx.z * sC;
    __shared__ float As[8][128];
    __shared__ float Bs[8][128];
    int t = threadIdx.x;
    int tx = t & 15, ty = t >> 4;
    int row0 = blockIdx.y * 128, col0 = blockIdx.x * 128;
    float acc[8][8];
#pragma unroll
    for (int i = 0; i < 8; i++)
#pragma unroll
        for (int j = 0; j < 8; j++) acc[i][j] = 0.f;

    for (int k0 = 0; k0 < K; k0 += 8) {
#pragma unroll
        for (int i = 0; i < 4; i++) {
            int idx = t + i * 256;
            int m = idx >> 3, k = idx & 7;
            float va = 0.f;
            if (row0 + m < M && k0 + k < K) va = Ab[(size_t)(row0 + m) * K + k0 + k];
            As[k][m] = va;
            int k2 = idx >> 7, n = idx & 127;
            float vb = 0.f;
            if (k0 + k2 < K && col0 + n < N) {
                vb = Bb[(size_t)(k0 + k2) * N + col0 + n];
                if (bnm) {
                    int ch = k0 + k2;
                    vb = (vb - bnm[ch]) * bnr[ch] * bng[ch] + bnb[ch];
                }
            }
            Bs[k2][n] = vb;
        }
        __syncthreads();
#pragma unroll
        for (int kk = 0; kk < 8; kk++) {
            float a[8], bv[8];
#pragma unroll
            for (int i = 0; i < 8; i++) a[i] = As[kk][ty * 8 + i];
#pragma unroll
            for (int j = 0; j < 8; j++) bv[j] = Bs[kk][tx * 8 + j];
#pragma unroll
            for (int i = 0; i < 8; i++)
#pragma unroll
                for (int j = 0; j < 8; j++)
                    acc[i][j] = fmaf(a[i], bv[j], acc[i][j]);
        }
        __syncthreads();
    }
#pragma unroll
    for (int i = 0; i < 8; i++) {
        int r = row0 + ty * 8 + i;
        if (r >= M) continue;
#pragma unroll
        for (int j = 0; j < 8; j++) {
            int cc = col0 + tx * 8 + j;
            if (cc < N) Cb[(size_t)r * N + cc] = acc[i][j];
        }
    }
}

// ---------------- tf32 tensor-core GEMM (exact-multiple dims) ----------------
// C(MxN) = A(MxK,row) @ B ; B normal: KxN row-major; bT: B is NxK row-major (C=A·B^T).
// Requires M%128==0, N%128==0, K%16==0, pointers 16B aligned.
// Optional per-k-channel BN affine (+leaky) applied to B elements (normal mode only).
__device__ __forceinline__ unsigned f2tf(float v) {
    unsigned r; asm("cvt.rna.tf32.f32 %0, %1;" : "=r"(r) : "f"(v)); return r;
}

#define TC_LD(k0) { \
    ra0 = *(const float4*)&Ab[(size_t)(row0+ar0)*K + (k0) + ak0]; \
    ra1 = *(const float4*)&Ab[(size_t)(row0+ar1)*K + (k0) + ak1]; \
    if (bT) { \
        rb0 = *(const float4*)&Bb[(size_t)(col0+ar0)*K + (k0) + ak0]; \
        rb1 = *(const float4*)&Bb[(size_t)(col0+ar1)*K + (k0) + ak1]; \
    } else { \
        rb0 = *(const float4*)&Bb[(size_t)((k0)+br0)*N + col0 + bc0]; \
        rb1 = *(const float4*)&Bb[(size_t)((k0)+br1)*N + col0 + bc1]; \
        if (bnm) { \
            int ch0 = (k0)+br0, ch1 = (k0)+br1; \
            float m0 = bnm[ch0], s0 = bnr[ch0]*bng[ch0], o0 = bnb[ch0]; \
            float m1 = bnm[ch1], s1 = bnr[ch1]*bng[ch1], o1 = bnb[ch1]; \
            rb0.x=(rb0.x-m0)*s0+o0; rb0.y=(rb0.y-m0)*s0+o0; rb0.z=(rb0.z-m0)*s0+o0; rb0.w=(rb0.w-m0)*s0+o0; \
            rb1.x=(rb1.x-m1)*s1+o1; rb1.y=(rb1.y-m1)*s1+o1; rb1.z=(rb1.z-m1)*s1+o1; rb1.w=(rb1.w-m1)*s1+o1; \
            if (leaky) { \
                rb0.x=rb0.x>0.f?rb0.x:0.2f*rb0.x; rb0.y=rb0.y>0.f?rb0.y:0.2f*rb0.y; \
                rb0.z=rb0.z>0.f?rb0.z:0.2f*rb0.z; rb0.w=rb0.w>0.f?rb0.w:0.2f*rb0.w; \
                rb1.x=rb1.x>0.f?rb1.x:0.2f*rb1.x; rb1.y=rb1.y>0.f?rb1.y:0.2f*rb1.y; \
                rb1.z=rb1.z>0.f?rb1.z:0.2f*rb1.z; rb1.w=rb1.w>0.f?rb1.w:0.2f*rb1.w; \
            } \
        } \
    } }

#define TC_ST() { \
    As[ak0+0][ar0]=f2tf(ra0.x); As[ak0+1][ar0]=f2tf(ra0.y); As[ak0+2][ar0]=f2tf(ra0.z); As[ak0+3][ar0]=f2tf(ra0.w); \
    As[ak1+0][ar1]=f2tf(ra1.x); As[ak1+1][ar1]=f2tf(ra1.y); As[ak1+2][ar1]=f2tf(ra1.z); As[ak1+3][ar1]=f2tf(ra1.w); \
    if (bT) { \
        Bs[ak0+0][ar0]=f2tf(rb0.x); Bs[ak0+1][ar0]=f2tf(rb0.y); Bs[ak0+2][ar0]=f2tf(rb0.z); Bs[ak0+3][ar0]=f2tf(rb0.w); \
        Bs[ak1+0][ar1]=f2tf(rb1.x); Bs[ak1+1][ar1]=f2tf(rb1.y); Bs[ak1+2][ar1]=f2tf(rb1.z); Bs[ak1+3][ar1]=f2tf(rb1.w); \
    } else { \
        Bs[br0][bc0+0]=f2tf(rb0.x); Bs[br0][bc0+1]=f2tf(rb0.y); Bs[br0][bc0+2]=f2tf(rb0.z); Bs[br0][bc0+3]=f2tf(rb0.w); \
        Bs[br1][bc1+0]=f2tf(rb1.x); Bs[br1][bc1+1]=f2tf(rb1.y); Bs[br1][bc1+2]=f2tf(rb1.z); Bs[br1][bc1+3]=f2tf(rb1.w); \
    } }

__global__ __launch_bounds__(256, 2) void k_gemm_tc(
    const float* __restrict__ A, const float* __restrict__ B, float* __restrict__ C,
    int M, int N, int K, size_t sA, size_t sB, size_t sC, int bT,
    const float* __restrict__ bnm, const float* __restrict__ bnr,
    const float* __restrict__ bng, const float* __restrict__ bnb, int leaky)
{
    __shared__ unsigned As[16][136];
    __shared__ unsigned Bs[16][136];
    const float* Ab = A + blockIdx.z * sA;
    const float* Bb = B + blockIdx.z * sB;
    float* Cb = C + blockIdx.z * sC;
    int t = threadIdx.x, lane = t & 31, wid = t >> 5;
    int g = lane >> 2, tid4 = lane & 3;
    int wm = (wid >> 2) * 64, wn = (wid & 3) * 32;
    int row0 = blockIdx.y * 128, col0 = blockIdx.x * 128;

    float acc[4][4][4];
#pragma unroll
    for (int i = 0; i < 4; i++)
#pragma unroll
        for (int j = 0; j < 4; j++)
#pragma unroll
            for (int r = 0; r < 4; r++) acc[i][j][r] = 0.f;

    int l0 = t, l1 = t + 256;
    int ar0 = l0 >> 2, ak0 = (l0 & 3) * 4;
    int ar1 = l1 >> 2, ak1 = (l1 & 3) * 4;
    int br0 = l0 >> 5, bc0 = (l0 & 31) * 4;
    int br1 = l1 >> 5, bc1 = (l1 & 31) * 4;

    float4 ra0, ra1, rb0, rb1;

    TC_LD(0);
    TC_ST();
    __syncthreads();

    for (int k0 = 0; k0 < K; k0 += 16) {
        int more = (k0 + 16) < K;
        if (more) TC_LD(k0 + 16);
#pragma unroll
        for (int ks = 0; ks < 16; ks += 8) {
            unsigned af[4][4], bf[4][2];
#pragma unroll
            for (int mf = 0; mf < 4; mf++) {
                int mb = wm + mf * 16 + g;
                af[mf][0] = As[ks + tid4][mb];
                af[mf][1] = As[ks + tid4][mb + 8];
                af[mf][2] = As[ks + tid4 + 4][mb];
                af[mf][3] = As[ks + tid4 + 4][mb + 8];
            }
#pragma unroll
            for (int nf = 0; nf < 4; nf++) {
                int nb = wn + nf * 8 + g;
                bf[nf][0] = Bs[ks + tid4][nb];
                bf[nf][1] = Bs[ks + tid4 + 4][nb];
            }
#pragma unroll
            for (int mf = 0; mf < 4; mf++)
#pragma unroll
                for (int nf = 0; nf < 4; nf++) {
                    asm volatile(
                        "mma.sync.aligned.m16n8k8.row.col.f32.tf32.tf32.f32 "
                        "{%0,%1,%2,%3}, {%4,%5,%6,%7}, {%8,%9}, {%0,%1,%2,%3};"
                        : "+f"(acc[mf][nf][0]), "+f"(acc[mf][nf][1]),
                          "+f"(acc[mf][nf][2]), "+f"(acc[mf][nf][3])
                        : "r"(af[mf][0]), "r"(af[mf][1]), "r"(af[mf][2]), "r"(af[mf][3]),
                          "r"(bf[nf][0]), "r"(bf[nf][1]));
                }
        }
        __syncthreads();
        if (more) { TC_ST(); __syncthreads(); }
    }

#pragma unroll
    for (int mf = 0; mf < 4; mf++) {
#pragma unroll
        for (int nf = 0; nf < 4; nf++) {
            size_t r0 = (size_t)(row0 + wm + mf * 16 + g);
            int c = col0 + wn + nf * 8 + tid4 * 2;
            *(float2*)&Cb[r0 * N + c]       = make_float2(acc[mf][nf][0], acc[mf][nf][1]);
            *(float2*)&Cb[(r0 + 8) * N + c] = make_float2(acc[mf][nf][2], acc[mf][nf][3]);
        }
    }
}

// ---------------- softmax with fused BN2 affine; writes select + row norm ----------------
__global__ void k_softmax(const float* __restrict__ g2, const float* __restrict__ b2) {
    int row = blockIdx.x;               // b*NP + s
    int s = row & (NP - 1);
    float mch = g_bnm[s], rch = g_bnr[s] * g2[s], bch = b2[s];
    float* x = g_h2 + (size_t)row * NN;
    int t = threadIdx.x;
    __shared__ float rs[256], rq[256];
    float m = -1e30f;
    for (int j = t; j < NN; j += 256) {
        float v = (x[j] - mch) * rch + bch;
        m = fmaxf(m, v);
    }
    rs[t] = m; __syncthreads();
    for (int o = 128; o > 0; o >>= 1) { if (t < o) rs[t] = fmaxf(rs[t], rs[t + o]); __syncthreads(); }
    m = rs[0]; __syncthreads();
    float ssum = 0.f, sq = 0.f;
    for (int j = t; j < NN; j += 256) {
        float v = (x[j] - mch) * rch + bch;
        float e = expf(v - m);
        x[j] = e;
        ssum += e; sq = fmaf(e, e, sq);
    }
    rs[t] = ssum; rq[t] = sq; __syncthreads();
    for (int o = 128; o > 0; o >>= 1) { if (t < o) { rs[t] += rs[t + o]; rq[t] += rq[t + o]; } __syncthreads(); }
    ssum = rs[0]; sq = rq[0];
    float inv = 1.f / ssum;
    for (int j = t; j < NN; j += 256) x[j] *= inv;
    if (t == 0) g_norm[row] = sqrtf(sq) * inv;
}

// ---------------- argmax (batch 0) + unique ----------------
__global__ void k_argmax() {
    int sidx = blockIdx.x;
    const float* x = g_h2 + (size_t)sidx * NN;
    int t = threadIdx.x;
    float bv = -1e30f; int bi = NN;
    for (int j = t; j < NN; j += 256) { float v = x[j]; if (v > bv) { bv = v; bi = j; } }
    __shared__ float rv[256]; __shared__ int ri[256];
    rv[t] = bv; ri[t] = bi; __syncthreads();
    for (int o = 128; o > 0; o >>= 1) {
        if (t < o) {
            if (rv[t + o] > rv[t] || (rv[t + o] == rv[t] && ri[t + o] < ri[t])) {
                rv[t] = rv[t + o]; ri[t] = ri[t + o];
            }
        }
        __syncthreads();
    }
    if (t == 0) g_amax[sidx] = ri[0];
}

__global__ void k_unique(float* __restrict__ out, int out_size) {
    __shared__ int fl[NN];
    __shared__ int rc[256];
    int t = threadIdx.x;
    for (int j = t; j < NN; j += 256) fl[j] = 0;
    __syncthreads();
    for (int s = t; s < NP; s += 256) fl[g_amax[s]] = 1;
    __syncthreads();
    int c = 0;
    for (int j = t; j < NN; j += 256) c += fl[j];
    rc[t] = c; __syncthreads();
    for (int o = 128; o > 0; o >>= 1) { if (t < o) rc[t] += rc[t + o]; __syncthreads(); }
    if (t == 0 && OUT_UNIQ < out_size) out[OUT_UNIQ] = (float)rc[0];
}

// ---------------- cos loss from materialized inner ----------------
__global__ void k_loss() {
    int b = blockIdx.x;
    int t = threadIdx.x;
    const float* inn = g_inner + (size_t)b * NP * NP;
    const float* nrm = g_norm + b * NP;
    float s = 0.f;
    for (int i = t; i < NP * NP; i += 256) {
        int ss = i >> 9, tt = i & (NP - 1);
        if (ss == tt) continue;
        float v = inn[i] / (nrm[ss] * nrm[tt] + 1e-10f);
        s = fmaf(v, v, s);
    }
    __shared__ float red[256];
    red[t] = s; __syncthreads();
    for (int o = 128; o > 0; o >>= 1) { if (t < o) red[t] += red[t + o]; __syncthreads(); }
    if (t == 0) g_losspart[b] = red[0];
}

__global__ void k_lossfin(float* __restrict__ out, int out_size) {
    if (threadIdx.x == 0 && OUT_LOSS < out_size) {
        float acc = 0.f;
        for (int b = 0; b < BB; b++) acc += sqrtf(g_losspart[b]);
        out[OUT_LOSS] = acc / (float)BB;
    }
}

// ---------------- gather ----------------
__global__ void k_gather() {
    int i = blockIdx.x * blockDim.x + threadIdx.x;
    if (i >= BB * NN * NS) return;
    int k = i % NS; int n = (i / NS) % NN; int b = i / (NS * NN);
    int id = g_idx[i];
    const float* src = g_agg + ((size_t)b * NN + id) * SCC;
    float* dp = g_gp + ((size_t)(b * NN + n)) * (NS * DD) + k * DD;
#pragma unroll 8
    for (int d = 0; d < DD; d++) dp[d] = src[d];
    float* dx = g_gx + ((size_t)(b * NN + n)) * (NS * 3) + k * 3;
    dx[0] = src[64]; dx[1] = src[65]; dx[2] = src[66];
}

// ---------------- pad conv0 weights to CH_P ----------------
__global__ void k_padw(const float* __restrict__ w) {
    int i = blockIdx.x * blockDim.x + threadIdx.x;
    if (i >= 128 * CH_P) return;
    int o = i / CH_P, c = i % CH_P;
    g_w0p[i] = (c < CH_IN) ? w[o * CH_IN + c] : 0.f;
}

// ---------------- edge build (B, CH_P, NS, NP) ----------------
__global__ void k_edge() {
    long long i = (long long)blockIdx.x * blockDim.x + threadIdx.x;
    long long tot = (long long)BB * CH_P * KS;
    if (i >= tot) return;
    int s = (int)(i % NP);
    int k = (int)((i / NP) % NS);
    int c = (int)((i / KS) % CH_P);
    int b = (int)(i / ((long long)CH_P * KS));
    const float* samp = g_samp + ((size_t)b * NP + s) * SCC;
    float v;
    if (c < 64) {
        v = samp[c];
    } else if (c < 128) {
        int d = c - 64;
        v = g_sgp[((size_t)b * NP + s) * (NS * DD) + k * DD + d] - samp[d];
    } else if (c < 131) {
        v = samp[64 + (c - 128)];
    } else if (c < 134) {
        int cc = c - 131;
        v = g_sgx[((size_t)b * NP + s) * (NS * 3) + k * 3 + cc] - samp[64 + cc];
    } else {
        v = 0.f;
    }
    g_edge[i] = v;
}

// ---------------- fused BN + leaky + maxpool on c2 ----------------
__global__ void k_bn_max(const float* __restrict__ g2, const float* __restrict__ b2,
                         float* __restrict__ out, int out_size) {
    int i = blockIdx.x * blockDim.x + threadIdx.x;   // B*256*NP
    if (i >= BB * 256 * NP) return;
    int s = i % NP; int o = (i / NP) % 256; int b = i / (256 * NP);
    float mch = g_bnm[o], rch = g_bnr[o] * g2[o], bch = b2[o];
    const float* p = g_c2 + ((size_t)b * 256 + o) * KS + s;
    float m = -1e30f;
#pragma unroll
    for (int k = 0; k < NS; k++) {
        float v = (p[k * NP] - mch) * rch + bch;
        v = v > 0.f ? v : 0.2f * v;
        m = fmaxf(m, v);
    }
    int oi = OUT_PTS + i;
    if (oi < out_size) out[oi] = m;
}

__global__ void k_wxyz(float* __restrict__ out, int out_size) {
    int i = blockIdx.x * blockDim.x + threadIdx.x;
    if (i >= BB * 3 * NP) return;
    int s = i % NP; int c = (i / NP) % 3; int b = i / (3 * NP);
    if (i < out_size) out[i] = g_samp[((size_t)b * NP + s) * SCC + 64 + c];
}

// ---------------- launch ----------------
extern "C" void kernel_launch(void* const* d_in, const int* in_sizes, int n_in,
                              void* d_out, int out_size) {
    const float* xyz   = (const float*)d_in[0];
    const float* pts   = (const float*)d_in[1];
    const float* w1_w  = (const float*)d_in[2];
    const float* bn1_g = (const float*)d_in[4];
    const float* bn1_b = (const float*)d_in[5];
    const float* w2_w  = (const float*)d_in[6];
    const float* bn2_g = (const float*)d_in[8];
    const float* bn2_b = (const float*)d_in[9];
    const float* c0w   = (const float*)d_in[10];
    const float* bg0   = (const float*)d_in[12];
    const float* bb0   = (const float*)d_in[13];
    const float* c1w   = (const float*)d_in[14];
    const float* bg1   = (const float*)d_in[16];
    const float* bb1   = (const float*)d_in[17];
    const float* c2w   = (const float*)d_in[18];
    const float* bg2   = (const float*)d_in[20];
    const float* bb2   = (const float*)d_in[21];
    float* out = (float*)d_out;

    float *p_agg, *p_h1, *p_h2, *p_samp, *p_gp, *p_gx, *p_sgp, *p_sgx, *p_inner,
          *p_edge, *p_w0p, *p_c0, *p_c1, *p_c2, *p_bnm, *p_bnr;
    cudaGetSymbolAddress((void**)&p_agg,   g_agg);
    cudaGetSymbolAddress((void**)&p_h1,    g_h1);
    cudaGetSymbolAddress((void**)&p_h2,    g_h2);
    cudaGetSymbolAddress((void**)&p_samp,  g_samp);
    cudaGetSymbolAddress((void**)&p_gp,    g_gp);
    cudaGetSymbolAddress((void**)&p_gx,    g_gx);
    cudaGetSymbolAddress((void**)&p_sgp,   g_sgp);
    cudaGetSymbolAddress((void**)&p_sgx,   g_sgx);
    cudaGetSymbolAddress((void**)&p_inner, g_inner);
    cudaGetSymbolAddress((void**)&p_edge,  g_edge);
    cudaGetSymbolAddress((void**)&p_w0p,   g_w0p);
    cudaGetSymbolAddress((void**)&p_c0,    g_c0);
    cudaGetSymbolAddress((void**)&p_c1,    g_c1);
    cudaGetSymbolAddress((void**)&p_c2,    g_c2);
    cudaGetSymbolAddress((void**)&p_bnm,   g_bnm);
    cudaGetSymbolAddress((void**)&p_bnr,   g_bnr);

    k_prep<<<(BB * NN + 255) / 256, 256>>>(xyz, pts);
    k_ballquery<<<dim3(NN / 256, BB), 256>>>();
    k_h1<<<dim3(NN / 256, SCC, BB), 256>>>(w1_w);
    k_bnstats<<<SCC, 256>>>(p_h1, SCC, NN);
    // h2 = w2 @ bn1(h1)   (fp32 generic, K=67, BN fused into B-load)
    k_sgemm<<<dim3(16, 4, BB), 256>>>(w2_w, p_h1, p_h2, NP, NN, SCC,
                                      0, (size_t)SCC * NN, (size_t)NP * NN,
                                      p_bnm, p_bnr, bn1_g, bn1_b);
    k_bnstats<<<NP, 256>>>(p_h2, NP, NN);
    k_softmax<<<BB * NP, 256>>>(bn2_g, bn2_b);
    k_argmax<<<NP, 256>>>();
    k_unique<<<1, 256>>>(out, out_size);
    // inner = sel @ sel^T  (tf32 tensor cores, NT mode)
    k_gemm_tc<<<dim3(NP / 128, NP / 128, BB), 256>>>(
        p_h2, p_h2, p_inner, NP, NP, NN,
        (size_t)NP * NN, (size_t)NP * NN, (size_t)NP * NP, 1,
        nullptr, nullptr, nullptr, nullptr, 0);
    k_loss<<<BB, 256>>>();
    k_lossfin<<<1, 1>>>(out, out_size);
    // samp = sel @ agg  (fp32 generic, N=67)
    k_sgemm<<<dim3(1, 4, BB), 256>>>(p_h2, p_agg, p_samp, NP, SCC, NN,
                                     (size_t)NP * NN, (size_t)NN * SCC, (size_t)NP * SCC,
                                     nullptr, nullptr, nullptr, nullptr);
    k_gather<<<(BB * NN * NS + 255) / 256, 256>>>();
    // sgp = sel @ gp  (tf32 TC; dominant GEMM)
    k_gemm_tc<<<dim3((NS * DD) / 128, NP / 128, BB), 256>>>(
        p_h2, p_gp, p_sgp, NP, NS * DD, NN,
        (size_t)NP * NN, (size_t)NN * NS * DD, (size_t)NP * NS * DD, 0,
        nullptr, nullptr, nullptr, nullptr, 0);
    // sgx = sel @ gx  (fp32 generic, N=96)
    k_sgemm<<<dim3(1, 4, BB), 256>>>(p_h2, p_gx, p_sgx, NP, NS * 3, NN,
                                     (size_t)NP * NN, (size_t)NN * NS * 3, (size_t)NP * NS * 3,
                                     nullptr, nullptr, nullptr, nullptr);
    k_padw<<<(128 * CH_P + 255) / 256, 256>>>(c0w);
    k_edge<<<(int)(((long long)BB * CH_P * KS + 255) / 256), 256>>>();
    // conv0 (tf32 TC, K=144)
    k_gemm_tc<<<dim3(KS / 128, 1, BB), 256>>>(
        p_w0p, p_edge, p_c0, 128, KS, CH_P,
        0, (size_t)CH_P * KS, (size_t)128 * KS, 0,
        nullptr, nullptr, nullptr, nullptr, 0);
    k_bnstats<<<128, 256>>>(p_c0, 128, KS);
    // conv1 (tf32 TC, BN0+leaky fused into B-load)
    k_gemm_tc<<<dim3(KS / 128, 1, BB), 256>>>(
        c1w, p_c0, p_c1, 128, KS, 128,
        0, (size_t)128 * KS, (size_t)128 * KS, 0,
        p_bnm, p_bnr, bg0, bb0, 1);
    k_bnstats<<<128, 256>>>(p_c1, 128, KS);
    // conv2 (tf32 TC, BN1+leaky fused)
    k_gemm_tc<<<dim3(KS / 128, 2, BB), 256>>>(
        c2w, p_c1, p_c2, 256, KS, 128,
        0, (size_t)128 * KS, (size_t)256 * KS, 0,
        p_bnm, p_bnr, bg1, bb1, 1);
    k_bnstats<<<256, 256>>>(p_c2, 256, KS);
    k_bn_max<<<(BB * 256 * NP + 255) / 256, 256>>>(bg2, bb2, out, out_size);
    k_wxyz<<<(BB * 3 * NP + 255) / 256, 256>>>(out, out_size);
}

// round 4
// speedup vs baseline: 2.6158x; 1.5258x over previous
#include <cuda_runtime.h>
#include <math.h>

#define BB    16
#define NN    2048
#define DD    64
#define NP    512
#define NS    32
#define SCC   67
#define CH_IN 134
#define CH_P  144
#define KS    (NS*NP)      /* 16384 */
#define GPX_N 2304         /* 32*68 + 128 pad block (agg at 2176) */
#define AGG0  2176
#define EPSBN 1e-5f
#define R2    0.04f

#define OUT_PTS   (BB*3*NP)
#define OUT_LOSS  (OUT_PTS + BB*256*NP)
#define OUT_UNIQ  (OUT_LOSS + 1)

// ---------------- scratch ----------------
__device__ float g_agg [BB*NN*SCC];
__device__ float g_xn  [BB*NN];
__device__ int   g_idx [BB*NN*NS];
__device__ float g_h1  [BB*SCC*NN];
__device__ float g_h2  [BB*NP*NN];
__device__ float g_norm[BB*NP];
__device__ float g_losspart[BB];
__device__ int   g_amax[NP];
__device__ float g_gpx [(size_t)BB*NN*GPX_N];     // 302MB
__device__ float g_spx [(size_t)BB*NP*GPX_N];     // 75MB
__device__ float g_inner[(size_t)BB*NP*NP];
__device__ float g_edge[(size_t)BB*CH_P*KS];
__device__ float g_w0p [128*CH_P];
__device__ float g_c0  [(size_t)BB*128*KS];
__device__ float g_c1  [(size_t)BB*128*KS];
__device__ float g_mx  [(size_t)BB*256*NP];
__device__ float g_mn  [(size_t)BB*256*NP];
__device__ float g_bnm [512];
__device__ float g_bnr [512];
__device__ float g_bnp_sum[512*2048];
__device__ float g_bnp_sq [512*2048];

// ---------------- prep ----------------
__global__ void k_prep(const float* __restrict__ xyz, const float* __restrict__ pts) {
    int i = blockIdx.x * blockDim.x + threadIdx.x;
    if (i >= BB * NN) return;
    int b = i / NN, n = i % NN;
    float* arow = g_agg + (size_t)i * SCC;
    const float* p = pts + (size_t)b * DD * NN + n;
#pragma unroll 8
    for (int d = 0; d < DD; d++) arow[d] = p[(size_t)d * NN];
    const float* x = xyz + (size_t)b * 3 * NN + n;
    float a = x[0], c = x[NN], e = x[2 * NN];
    arow[64] = a; arow[65] = c; arow[66] = e;
    g_xn[i] = fmaf(e, e, fmaf(c, c, a * a));
}

// ---------------- ball query ----------------
__global__ void k_ballquery() {
    __shared__ float sx[NN], sy[NN], sz[NN], sn[NN];
    int b = blockIdx.y;
    int t = threadIdx.x;
    for (int j = t; j < NN; j += blockDim.x) {
        const float* a = g_agg + ((size_t)b * NN + j) * SCC;
        sx[j] = a[64]; sy[j] = a[65]; sz[j] = a[66];
        sn[j] = g_xn[b * NN + j];
    }
    __syncthreads();
    int n = blockIdx.x * blockDim.x + t;
    float px = sx[n], py = sy[n], pz = sz[n], pn = sn[n];
    int base = (b * NN + n) * NS;
    int cnt = 0, first = 0;
    for (int m = 0; m < NN && cnt < NS; m++) {
        float dot = fmaf(px, sx[m], fmaf(py, sy[m], pz * sz[m]));
        float d = pn + sn[m] - 2.0f * dot;
        if (!(d > R2)) {
            if (cnt == 0) first = m;
            g_idx[base + cnt] = m;
            cnt++;
        }
    }
    for (int j = cnt; j < NS; j++) g_idx[base + j] = first;
}

// ---------------- h1 = w1 @ agg ----------------
__global__ void k_h1(const float* __restrict__ w1) {
    __shared__ float w[SCC];
    int o = blockIdx.y, b = blockIdx.z;
    if (threadIdx.x < SCC) w[threadIdx.x] = w1[o * SCC + threadIdx.x];
    __syncthreads();
    int n = blockIdx.x * blockDim.x + threadIdx.x;
    const float* arow = g_agg + ((size_t)(b * NN + n)) * SCC;
    float s = 0.f;
#pragma unroll 1
    for (int c = 0; c < SCC; c++) s = fmaf(w[c], arow[c], s);
    g_h1[((size_t)b * SCC + o) * NN + n] = s;
}

// ---------------- BN stats (small tensors only: h1, h2) ----------------
__global__ void k_bnstats(const float* __restrict__ x, int C, int S) {
    int c = blockIdx.x, t = threadIdx.x;
    float s = 0.f, sq = 0.f;
    for (int b = 0; b < BB; b++) {
        const float* p = x + ((size_t)b * C + c) * S;
        for (int j = t; j < S; j += 256) { float v = p[j]; s += v; sq = fmaf(v, v, sq); }
    }
    __shared__ float rs[256], rq[256];
    rs[t] = s; rq[t] = sq; __syncthreads();
    for (int o = 128; o > 0; o >>= 1) {
        if (t < o) { rs[t] += rs[t + o]; rq[t] += rq[t + o]; }
        __syncthreads();
    }
    if (t == 0) {
        float cnt = (float)BB * (float)S;
        float m = rs[0] / cnt;
        float v = rq[0] / cnt - m * m;
        g_bnm[c] = m;
        g_bnr[c] = rsqrtf(fmaxf(v, 0.f) + EPSBN);
    }
}

// ---------------- reduce TC partial stats -> bnm/bnr ----------------
__global__ void k_bnfin(int P, float count) {
    int c = blockIdx.x, t = threadIdx.x;
    float s = 0.f, sq = 0.f;
    const float* ps = g_bnp_sum + (size_t)c * 2048;
    const float* pq = g_bnp_sq  + (size_t)c * 2048;
    for (int j = t; j < P; j += 256) { s += ps[j]; sq += pq[j]; }
    __shared__ float rs[256], rq[256];
    rs[t] = s; rq[t] = sq; __syncthreads();
    for (int o = 128; o > 0; o >>= 1) {
        if (t < o) { rs[t] += rs[t + o]; rq[t] += rq[t + o]; }
        __syncthreads();
    }
    if (t == 0) {
        float m = rs[0] / count;
        float v = rq[0] / count - m * m;
        g_bnm[c] = m;
        g_bnr[c] = rsqrtf(fmaxf(v, 0.f) + EPSBN);
    }
}

// ---------------- generic fp32 SGEMM (h2 only), BN fused on B ----------------
__global__ __launch_bounds__(256) void k_sgemm(
    const float* __restrict__ A, const float* __restrict__ Bm, float* __restrict__ C,
    int M, int N, int K, size_t sA, size_t sB, size_t sC,
    const float* __restrict__ bnm, const float* __restrict__ bnr,
    const float* __restrict__ bng, const float* __restrict__ bnb)
{
    const float* Ab = A + blockIdx.z * sA;
    const float* Bb = Bm + blockIdx.z * sB;
    float* Cb = C + blockIdx.z * sC;
    __shared__ float As[8][128];
    __shared__ float Bs[8][128];
    int t = threadIdx.x;
    int tx = t & 15, ty = t >> 4;
    int row0 = blockIdx.y * 128, col0 = blockIdx.x * 128;
    float acc[8][8];
#pragma unroll
    for (int i = 0; i < 8; i++)
#pragma unroll
        for (int j = 0; j < 8; j++) acc[i][j] = 0.f;

    for (int k0 = 0; k0 < K; k0 += 8) {
#pragma unroll
        for (int i = 0; i < 4; i++) {
            int idx = t + i * 256;
            int m = idx >> 3, k = idx & 7;
            float va = 0.f;
            if (row0 + m < M && k0 + k < K) va = Ab[(size_t)(row0 + m) * K + k0 + k];
            As[k][m] = va;
            int k2 = idx >> 7, n = idx & 127;
            float vb = 0.f;
            if (k0 + k2 < K && col0 + n < N) {
                vb = Bb[(size_t)(k0 + k2) * N + col0 + n];
                if (bnm) {
                    int ch = k0 + k2;
                    vb = (vb - bnm[ch]) * bnr[ch] * bng[ch] + bnb[ch];
                }
            }
            Bs[k2][n] = vb;
        }
        __syncthreads();
#pragma unroll
        for (int kk = 0; kk < 8; kk++) {
            float a[8], bv[8];
#pragma unroll
            for (int i = 0; i < 8; i++) a[i] = As[kk][ty * 8 + i];
#pragma unroll
            for (int j = 0; j < 8; j++) bv[j] = Bs[kk][tx * 8 + j];
#pragma unroll
            for (int i = 0; i < 8; i++)
#pragma unroll
                for (int j = 0; j < 8; j++)
                    acc[i][j] = fmaf(a[i], bv[j], acc[i][j]);
        }
        __syncthreads();
    }
#pragma unroll
    for (int i = 0; i < 8; i++) {
        int r = row0 + ty * 8 + i;
        if (r >= M) continue;
#pragma unroll
        for (int j = 0; j < 8; j++) {
            int cc = col0 + tx * 8 + j;
            if (cc < N) Cb[(size_t)r * N + cc] = acc[i][j];
        }
    }
}

// ---------------- tf32 tensor-core GEMM ----------------
__device__ __forceinline__ unsigned f2tf(float v) {
    unsigned r; asm("cvt.rna.tf32.f32 %0, %1;" : "=r"(r) : "f"(v)); return r;
}

#define TC_LD(k0) { \
    ra0 = *(const float4*)&Ab[(size_t)(row0+ar0)*K + (k0) + ak0]; \
    ra1 = *(const float4*)&Ab[(size_t)(row0+ar1)*K + (k0) + ak1]; \
    if (bT) { \
        rb0 = *(const float4*)&Bb[(size_t)(col0+ar0)*K + (k0) + ak0]; \
        rb1 = *(const float4*)&Bb[(size_t)(col0+ar1)*K + (k0) + ak1]; \
    } else { \
        rb0 = *(const float4*)&Bb[(size_t)((k0)+br0)*N + col0 + bc0]; \
        rb1 = *(const float4*)&Bb[(size_t)((k0)+br1)*N + col0 + bc1]; \
        if (bnm) { \
            int ch0 = (k0)+br0, ch1 = (k0)+br1; \
            if (ch0 < bnC) { \
                float m0 = bnm[ch0], s0 = bnr[ch0]*bng[ch0], o0 = bnb[ch0]; \
                rb0.x=(rb0.x-m0)*s0+o0; rb0.y=(rb0.y-m0)*s0+o0; rb0.z=(rb0.z-m0)*s0+o0; rb0.w=(rb0.w-m0)*s0+o0; \
                if (leaky) { \
                    rb0.x=rb0.x>0.f?rb0.x:0.2f*rb0.x; rb0.y=rb0.y>0.f?rb0.y:0.2f*rb0.y; \
                    rb0.z=rb0.z>0.f?rb0.z:0.2f*rb0.z; rb0.w=rb0.w>0.f?rb0.w:0.2f*rb0.w; \
                } \
            } else { rb0.x=rb0.y=rb0.z=rb0.w=0.f; } \
            if (ch1 < bnC) { \
                float m1 = bnm[ch1], s1 = bnr[ch1]*bng[ch1], o1 = bnb[ch1]; \
                rb1.x=(rb1.x-m1)*s1+o1; rb1.y=(rb1.y-m1)*s1+o1; rb1.z=(rb1.z-m1)*s1+o1; rb1.w=(rb1.w-m1)*s1+o1; \
                if (leaky) { \
                    rb1.x=rb1.x>0.f?rb1.x:0.2f*rb1.x; rb1.y=rb1.y>0.f?rb1.y:0.2f*rb1.y; \
                    rb1.z=rb1.z>0.f?rb1.z:0.2f*rb1.z; rb1.w=rb1.w>0.f?rb1.w:0.2f*rb1.w; \
                } \
            } else { rb1.x=rb1.y=rb1.z=rb1.w=0.f; } \
        } \
    } }

#define TC_ST() { \
    As[ak0+0][ar0]=f2tf(ra0.x); As[ak0+1][ar0]=f2tf(ra0.y); As[ak0+2][ar0]=f2tf(ra0.z); As[ak0+3][ar0]=f2tf(ra0.w); \
    As[ak1+0][ar1]=f2tf(ra1.x); As[ak1+1][ar1]=f2tf(ra1.y); As[ak1+2][ar1]=f2tf(ra1.z); As[ak1+3][ar1]=f2tf(ra1.w); \
    if (bT) { \
        Bs[ak0+0][ar0]=f2tf(rb0.x); Bs[ak0+1][ar0]=f2tf(rb0.y); Bs[ak0+2][ar0]=f2tf(rb0.z); Bs[ak0+3][ar0]=f2tf(rb0.w); \
        Bs[ak1+0][ar1]=f2tf(rb1.x); Bs[ak1+1][ar1]=f2tf(rb1.y); Bs[ak1+2][ar1]=f2tf(rb1.z); Bs[ak1+3][ar1]=f2tf(rb1.w); \
    } else { \
        Bs[br0][bc0+0]=f2tf(rb0.x); Bs[br0][bc0+1]=f2tf(rb0.y); Bs[br0][bc0+2]=f2tf(rb0.z); Bs[br0][bc0+3]=f2tf(rb0.w); \
        Bs[br1][bc1+0]=f2tf(rb1.x); Bs[br1][bc1+1]=f2tf(rb1.y); Bs[br1][bc1+2]=f2tf(rb1.z); Bs[br1][bc1+3]=f2tf(rb1.w); \
    } }

// C may be null (conv2: only maxmin+stats epilogues).
__global__ __launch_bounds__(256, 2) void k_gemm_tc(
    const float* __restrict__ A, const float* __restrict__ B, float* __restrict__ C,
    int M, int N, int K, size_t sA, size_t sB, size_t sC, int bT,
    const float* __restrict__ bnm, const float* __restrict__ bnr,
    const float* __restrict__ bng, const float* __restrict__ bnb, int bnC, int leaky,
    float* __restrict__ bnp_sum, float* __restrict__ bnp_sq, int P,
    float* __restrict__ mxp, float* __restrict__ mnp)
{
    __shared__ unsigned As[16][136];
    __shared__ unsigned Bs[16][136];
    __shared__ float ssum[8][64];
    __shared__ float ssq [8][64];
    const float* Ab = A + blockIdx.z * sA;
    const float* Bb = B + blockIdx.z * sB;
    int t = threadIdx.x, lane = t & 31, wid = t >> 5;
    int g = lane >> 2, tid4 = lane & 3;
    int wm = (wid >> 2) * 64, wn = (wid & 3) * 32;
    int row0 = blockIdx.y * 128, col0 = blockIdx.x * 128;

    float acc[4][4][4];
#pragma unroll
    for (int i = 0; i < 4; i++)
#pragma unroll
        for (int j = 0; j < 4; j++)
#pragma unroll
            for (int r = 0; r < 4; r++) acc[i][j][r] = 0.f;

    int l0 = t, l1 = t + 256;
    int ar0 = l0 >> 2, ak0 = (l0 & 3) * 4;
    int ar1 = l1 >> 2, ak1 = (l1 & 3) * 4;
    int br0 = l0 >> 5, bc0 = (l0 & 31) * 4;
    int br1 = l1 >> 5, bc1 = (l1 & 31) * 4;

    float4 ra0, ra1, rb0, rb1;

    TC_LD(0);
    TC_ST();
    __syncthreads();

    for (int k0 = 0; k0 < K; k0 += 16) {
        int more = (k0 + 16) < K;
        if (more) TC_LD(k0 + 16);
#pragma unroll
        for (int ks = 0; ks < 16; ks += 8) {
            unsigned af[4][4], bf[4][2];
#pragma unroll
            for (int mf = 0; mf < 4; mf++) {
                int mb = wm + mf * 16 + g;
                af[mf][0] = As[ks + tid4][mb];
                af[mf][1] = As[ks + tid4][mb + 8];
                af[mf][2] = As[ks + tid4 + 4][mb];
                af[mf][3] = As[ks + tid4 + 4][mb + 8];
            }
#pragma unroll
            for (int nf = 0; nf < 4; nf++) {
                int nb = wn + nf * 8 + g;
                bf[nf][0] = Bs[ks + tid4][nb];
                bf[nf][1] = Bs[ks + tid4 + 4][nb];
            }
#pragma unroll
            for (int mf = 0; mf < 4; mf++)
#pragma unroll
                for (int nf = 0; nf < 4; nf++) {
                    asm volatile(
                        "mma.sync.aligned.m16n8k8.row.col.f32.tf32.tf32.f32 "
                        "{%0,%1,%2,%3}, {%4,%5,%6,%7}, {%8,%9}, {%0,%1,%2,%3};"
                        : "+f"(acc[mf][nf][0]), "+f"(acc[mf][nf][1]),
                          "+f"(acc[mf][nf][2]), "+f"(acc[mf][nf][3])
                        : "r"(af[mf][0]), "r"(af[mf][1]), "r"(af[mf][2]), "r"(af[mf][3]),
                          "r"(bf[nf][0]), "r"(bf[nf][1]));
                }
        }
        __syncthreads();
        if (more) { TC_ST(); __syncthreads(); }
    }

    if (C) {
        float* Cb = C + blockIdx.z * sC;
#pragma unroll
        for (int mf = 0; mf < 4; mf++) {
#pragma unroll
            for (int nf = 0; nf < 4; nf++) {
                size_t r0 = (size_t)(row0 + wm + mf * 16 + g);
                int c = col0 + wn + nf * 8 + tid4 * 2;
                *(float2*)&Cb[r0 * N + c]       = make_float2(acc[mf][nf][0], acc[mf][nf][1]);
                *(float2*)&Cb[(r0 + 8) * N + c] = make_float2(acc[mf][nf][2], acc[mf][nf][3]);
            }
        }
    }

    if (mxp) {
        // cols are s*32+k ordered; each warp's 32 cols = one s
        int s = (col0 + wn) >> 5;
#pragma unroll
        for (int mf = 0; mf < 4; mf++) {
            float M0 = -1e30f, m0 = 1e30f, M1 = -1e30f, m1 = 1e30f;
#pragma unroll
            for (int nf = 0; nf < 4; nf++) {
                M0 = fmaxf(M0, fmaxf(acc[mf][nf][0], acc[mf][nf][1]));
                m0 = fminf(m0, fminf(acc[mf][nf][0], acc[mf][nf][1]));
                M1 = fmaxf(M1, fmaxf(acc[mf][nf][2], acc[mf][nf][3]));
                m1 = fminf(m1, fminf(acc[mf][nf][2], acc[mf][nf][3]));
            }
            M0 = fmaxf(M0, __shfl_xor_sync(~0u, M0, 1)); M0 = fmaxf(M0, __shfl_xor_sync(~0u, M0, 2));
            m0 = fminf(m0, __shfl_xor_sync(~0u, m0, 1)); m0 = fminf(m0, __shfl_xor_sync(~0u, m0, 2));
            M1 = fmaxf(M1, __shfl_xor_sync(~0u, M1, 1)); M1 = fmaxf(M1, __shfl_xor_sync(~0u, M1, 2));
            m1 = fminf(m1, __shfl_xor_sync(~0u, m1, 1)); m1 = fminf(m1, __shfl_xor_sync(~0u, m1, 2));
            if (tid4 == 0) {
                int r = row0 + wm + mf * 16 + g;
                size_t o1 = ((size_t)blockIdx.z * M + r) * (N >> 5) + s;
                size_t o2 = ((size_t)blockIdx.z * M + r + 8) * (N >> 5) + s;
                mxp[o1] = M0; mnp[o1] = m0;
                mxp[o2] = M1; mnp[o2] = m1;
            }
        }
    }

    if (bnp_sum) {
#pragma unroll
        for (int mf = 0; mf < 4; mf++) {
            float s0 = 0.f, q0 = 0.f, s1 = 0.f, q1 = 0.f;
#pragma unroll
            for (int nf = 0; nf < 4; nf++) {
                float a = acc[mf][nf][0], b = acc[mf][nf][1];
                float c = acc[mf][nf][2], d = acc[mf][nf][3];
                s0 += a + b; q0 += a * a + b * b;
                s1 += c + d; q1 += c * c + d * d;
            }
            s0 += __shfl_xor_sync(~0u, s0, 1); s0 += __shfl_xor_sync(~0u, s0, 2);
            q0 += __shfl_xor_sync(~0u, q0, 1); q0 += __shfl_xor_sync(~0u, q0, 2);
            s1 += __shfl_xor_sync(~0u, s1, 1); s1 += __shfl_xor_sync(~0u, s1, 2);
            q1 += __shfl_xor_sync(~0u, q1, 1); q1 += __shfl_xor_sync(~0u, q1, 2);
            if (tid4 == 0) {
                ssum[wid][mf * 16 + g] = s0;     ssq[wid][mf * 16 + g] = q0;
                ssum[wid][mf * 16 + g + 8] = s1; ssq[wid][mf * 16 + g + 8] = q1;
            }
        }
        __syncthreads();
        if (t < 128) {
            int half = t >> 6, lr = t & 63;
            float s = ssum[half * 4 + 0][lr] + ssum[half * 4 + 1][lr]
                    + ssum[half * 4 + 2][lr] + ssum[half * 4 + 3][lr];
            float q = ssq[half * 4 + 0][lr] + ssq[half * 4 + 1][lr]
                    + ssq[half * 4 + 2][lr] + ssq[half * 4 + 3][lr];
            int ch = row0 + t;
            int slot = (int)(blockIdx.z * gridDim.x + blockIdx.x);
            bnp_sum[(size_t)ch * 2048 + slot] = s;
            bnp_sq [(size_t)ch * 2048 + slot] = q;
        }
    }
}

// ---------------- softmax (fused BN2 affine) ----------------
__global__ void k_softmax(const float* __restrict__ g2, const float* __restrict__ b2) {
    int row = blockIdx.x;
    int s = row & (NP - 1);
    float mch = g_bnm[s], rch = g_bnr[s] * g2[s], bch = b2[s];
    float* x = g_h2 + (size_t)row * NN;
    int t = threadIdx.x;
    __shared__ float rs[256], rq[256];
    float m = -1e30f;
    for (int j = t; j < NN; j += 256) {
        float v = (x[j] - mch) * rch + bch;
        m = fmaxf(m, v);
    }
    rs[t] = m; __syncthreads();
    for (int o = 128; o > 0; o >>= 1) { if (t < o) rs[t] = fmaxf(rs[t], rs[t + o]); __syncthreads(); }
    m = rs[0]; __syncthreads();
    float ssum = 0.f, sq = 0.f;
    for (int j = t; j < NN; j += 256) {
        float v = (x[j] - mch) * rch + bch;
        float e = expf(v - m);
        x[j] = e;
        ssum += e; sq = fmaf(e, e, sq);
    }
    rs[t] = ssum; rq[t] = sq; __syncthreads();
    for (int o = 128; o > 0; o >>= 1) { if (t < o) { rs[t] += rs[t + o]; rq[t] += rq[t + o]; } __syncthreads(); }
    ssum = rs[0]; sq = rq[0];
    float inv = 1.f / ssum;
    for (int j = t; j < NN; j += 256) x[j] *= inv;
    if (t == 0) g_norm[row] = sqrtf(sq) * inv;
}

// ---------------- argmax + unique ----------------
__global__ void k_argmax() {
    int sidx = blockIdx.x;
    const float* x = g_h2 + (size_t)sidx * NN;
    int t = threadIdx.x;
    float bv = -1e30f; int bi = NN;
    for (int j = t; j < NN; j += 256) { float v = x[j]; if (v > bv) { bv = v; bi = j; } }
    __shared__ float rv[256]; __shared__ int ri[256];
    rv[t] = bv; ri[t] = bi; __syncthreads();
    for (int o = 128; o > 0; o >>= 1) {
        if (t < o) {
            if (rv[t + o] > rv[t] || (rv[t + o] == rv[t] && ri[t + o] < ri[t])) {
                rv[t] = rv[t + o]; ri[t] = ri[t + o];
            }
        }
        __syncthreads();
    }
    if (t == 0) g_amax[sidx] = ri[0];
}

__global__ void k_unique(float* __restrict__ out, int out_size) {
    __shared__ int fl[NN];
    __shared__ int rc[256];
    int t = threadIdx.x;
    for (int j = t; j < NN; j += 256) fl[j] = 0;
    __syncthreads();
    for (int s = t; s < NP; s += 256) fl[g_amax[s]] = 1;
    __syncthreads();
    int c = 0;
    for (int j = t; j < NN; j += 256) c += fl[j];
    rc[t] = c; __syncthreads();
    for (int o = 128; o > 0; o >>= 1) { if (t < o) rc[t] += rc[t + o]; __syncthreads(); }
    if (t == 0 && OUT_UNIQ < out_size) out[OUT_UNIQ] = (float)rc[0];
}

// ---------------- cos loss ----------------
__global__ void k_loss() {
    int b = blockIdx.x;
    int t = threadIdx.x;
    const float* inn = g_inner + (size_t)b * NP * NP;
    const float* nrm = g_norm + b * NP;
    float s = 0.f;
    for (int i = t; i < NP * NP; i += 256) {
        int ss = i >> 9, tt = i & (NP - 1);
        if (ss == tt) continue;
        float v = inn[i] / (nrm[ss] * nrm[tt] + 1e-10f);
        s = fmaf(v, v, s);
    }
    __shared__ float red[256];
    red[t] = s; __syncthreads();
    for (int o = 128; o > 0; o >>= 1) { if (t < o) red[t] += red[t + o]; __syncthreads(); }
    if (t == 0) g_losspart[b] = red[0];
}

__global__ void k_lossfin(float* __restrict__ out, int out_size) {
    if (threadIdx.x == 0 && OUT_LOSS < out_size) {
        float acc = 0.f;
        for (int b = 0; b < BB; b++) acc += sqrtf(g_losspart[b]);
        out[OUT_LOSS] = acc / (float)BB;
    }
}

// ---------------- gather -> gpx cols [k*68 .. k*68+67] ----------------
__global__ void k_gather() {
    int i = blockIdx.x * blockDim.x + threadIdx.x;
    if (i >= BB * NN * NS) return;
    int k = i % NS; int n = (i / NS) % NN; int b = i / (NS * NN);
    int id = g_idx[i];
    const float* src = g_agg + ((size_t)b * NN + id) * SCC;
    float* dst = g_gpx + ((size_t)(b * NN + n)) * GPX_N + k * 68;
#pragma unroll
    for (int d = 0; d < 64; d += 4) {
        float4 v = make_float4(src[d], src[d + 1], src[d + 2], src[d + 3]);
        *(float4*)&dst[d] = v;
    }
    *(float4*)&dst[64] = make_float4(src[64], src[65], src[66], 0.f);
}

// ---------------- agg copy -> gpx cols [2176 .. 2303] ----------------
__global__ void k_aggcopy() {
    int i = blockIdx.x * blockDim.x + threadIdx.x;
    if (i >= BB * NN) return;
    const float* src = g_agg + (size_t)i * SCC;
    float* dst = g_gpx + (size_t)i * GPX_N + AGG0;
#pragma unroll
    for (int c = 0; c < 128; c += 4) {
        float4 v;
        v.x = (c + 0 < SCC) ? src[c + 0] : 0.f;
        v.y = (c + 1 < SCC) ? src[c + 1] : 0.f;
        v.z = (c + 2 < SCC) ? src[c + 2] : 0.f;
        v.w = (c + 3 < SCC) ? src[c + 3] : 0.f;
        *(float4*)&dst[c] = v;
    }
}

// ---------------- pad conv0 weights ----------------
__global__ void k_padw(const float* __restrict__ w) {
    int i = blockIdx.x * blockDim.x + threadIdx.x;
    if (i >= 128 * CH_P) return;
    int o = i / CH_P, c = i % CH_P;
    g_w0p[i] = (c < CH_IN) ? w[o * CH_IN + c] : 0.f;
}

// ---------------- edge build (B, CH_P, s*32+k) from spx ----------------
__global__ void k_edge() {
    long long i = (long long)blockIdx.x * blockDim.x + threadIdx.x;
    long long tot = (long long)BB * CH_P * KS;
    if (i >= tot) return;
    int col = (int)(i % KS);
    int c = (int)((i / KS) % CH_P);
    int b = (int)(i / ((long long)CH_P * KS));
    int k = col & 31, s = col >> 5;
    const float* sp = g_spx + ((size_t)b * NP + s) * GPX_N;
    float v;
    if (c < 64) {
        v = sp[AGG0 + c];
    } else if (c < 128) {
        int d = c - 64;
        v = sp[k * 68 + d] - sp[AGG0 + d];
    } else if (c < 131) {
        v = sp[AGG0 + 64 + (c - 128)];
    } else if (c < 134) {
        int cc = c - 131;
        v = sp[k * 68 + 64 + cc] - sp[AGG0 + 64 + cc];
    } else {
        v = 0.f;
    }
    g_edge[i] = v;
}

// ---------------- final: BN + leaky on max/min, pick true max ----------------
__global__ void k_bn_max(const float* __restrict__ g2, const float* __restrict__ b2,
                         float* __restrict__ out, int out_size) {
    int i = blockIdx.x * blockDim.x + threadIdx.x;   // B*256*NP
    if (i >= BB * 256 * NP) return;
    int o = (i / NP) % 256;
    float mch = g_bnm[o], rch = g_bnr[o] * g2[o], bch = b2[o];
    float v1 = (g_mx[i] - mch) * rch + bch;
    float v2 = (g_mn[i] - mch) * rch + bch;
    v1 = v1 > 0.f ? v1 : 0.2f * v1;
    v2 = v2 > 0.f ? v2 : 0.2f * v2;
    int oi = OUT_PTS + i;
    if (oi < out_size) out[oi] = fmaxf(v1, v2);
}

__global__ void k_wxyz(float* __restrict__ out, int out_size) {
    int i = blockIdx.x * blockDim.x + threadIdx.x;
    if (i >= BB * 3 * NP) return;
    int s = i % NP; int c = (i / NP) % 3; int b = i / (3 * NP);
    if (i < out_size) out[i] = g_spx[((size_t)b * NP + s) * GPX_N + AGG0 + 64 + c];
}

// ---------------- launch ----------------
extern "C" void kernel_launch(void* const* d_in, const int* in_sizes, int n_in,
                              void* d_out, int out_size) {
    const float* xyz   = (const float*)d_in[0];
    const float* pts   = (const float*)d_in[1];
    const float* w1_w  = (const float*)d_in[2];
    const float* bn1_g = (const float*)d_in[4];
    const float* bn1_b = (const float*)d_in[5];
    const float* w2_w  = (const float*)d_in[6];
    const float* bn2_g = (const float*)d_in[8];
    const float* bn2_b = (const float*)d_in[9];
    const float* c0w   = (const float*)d_in[10];
    const float* bg0   = (const float*)d_in[12];
    const float* bb0   = (const float*)d_in[13];
    const float* c1w   = (const float*)d_in[14];
    const float* bg1   = (const float*)d_in[16];
    const float* bb1   = (const float*)d_in[17];
    const float* c2w   = (const float*)d_in[18];
    const float* bg2   = (const float*)d_in[20];
    const float* bb2   = (const float*)d_in[21];
    float* out = (float*)d_out;

    float *p_agg, *p_h1, *p_h2, *p_gpx, *p_spx, *p_inner, *p_edge, *p_w0p,
          *p_c0, *p_c1, *p_mx, *p_mn, *p_bnm, *p_bnr, *p_bps, *p_bpq;
    cudaGetSymbolAddress((void**)&p_agg,   g_agg);
    cudaGetSymbolAddress((void**)&p_h1,    g_h1);
    cudaGetSymbolAddress((void**)&p_h2,    g_h2);
    cudaGetSymbolAddress((void**)&p_gpx,   g_gpx);
    cudaGetSymbolAddress((void**)&p_spx,   g_spx);
    cudaGetSymbolAddress((void**)&p_inner, g_inner);
    cudaGetSymbolAddress((void**)&p_edge,  g_edge);
    cudaGetSymbolAddress((void**)&p_w0p,   g_w0p);
    cudaGetSymbolAddress((void**)&p_c0,    g_c0);
    cudaGetSymbolAddress((void**)&p_c1,    g_c1);
    cudaGetSymbolAddress((void**)&p_mx,    g_mx);
    cudaGetSymbolAddress((void**)&p_mn,    g_mn);
    cudaGetSymbolAddress((void**)&p_bnm,   g_bnm);
    cudaGetSymbolAddress((void**)&p_bnr,   g_bnr);
    cudaGetSymbolAddress((void**)&p_bps,   g_bnp_sum);
    cudaGetSymbolAddress((void**)&p_bpq,   g_bnp_sq);

    k_prep<<<(BB * NN + 255) / 256, 256>>>(xyz, pts);
    k_ballquery<<<dim3(NN / 256, BB), 256>>>();
    k_h1<<<dim3(NN / 256, SCC, BB), 256>>>(w1_w);
    k_bnstats<<<SCC, 256>>>(p_h1, SCC, NN);
    // h2 = w2 @ bn1(h1)  (fp32, BN fused)
    k_sgemm<<<dim3(16, 4, BB), 256>>>(w2_w, p_h1, p_h2, NP, NN, SCC,
                                      0, (size_t)SCC * NN, (size_t)NP * NN,
                                      p_bnm, p_bnr, bn1_g, bn1_b);
    k_bnstats<<<NP, 256>>>(p_h2, NP, NN);
    k_softmax<<<BB * NP, 256>>>(bn2_g, bn2_b);
    k_argmax<<<NP, 256>>>();
    k_unique<<<1, 256>>>(out, out_size);
    // inner = sel @ sel^T (tf32 NT)
    k_gemm_tc<<<dim3(NP / 128, NP / 128, BB), 256>>>(
        p_h2, p_h2, p_inner, NP, NP, NN,
        (size_t)NP * NN, (size_t)NP * NN, (size_t)NP * NP, 1,
        nullptr, nullptr, nullptr, nullptr, 0, 0,
        nullptr, nullptr, 0, nullptr, nullptr);
    k_loss<<<BB, 256>>>();
    k_lossfin<<<1, 1>>>(out, out_size);
    // build gpx, then one merged GEMM: spx = sel @ gpx (sgp | sgx | samp)
    k_gather<<<(BB * NN * NS + 255) / 256, 256>>>();
    k_aggcopy<<<(BB * NN + 255) / 256, 256>>>();
    k_gemm_tc<<<dim3(GPX_N / 128, NP / 128, BB), 256>>>(
        p_h2, p_gpx, p_spx, NP, GPX_N, NN,
        (size_t)NP * NN, (size_t)NN * GPX_N, (size_t)NP * GPX_N, 0,
        nullptr, nullptr, nullptr, nullptr, 0, 0,
        nullptr, nullptr, 0, nullptr, nullptr);
    k_padw<<<(128 * CH_P + 255) / 256, 256>>>(c0w);
    k_edge<<<(int)(((long long)BB * CH_P * KS + 255) / 256), 256>>>();
    // conv0 (stats epilogue)
    k_gemm_tc<<<dim3(KS / 128, 1, BB), 256>>>(
        p_w0p, p_edge, p_c0, 128, KS, CH_P,
        0, (size_t)CH_P * KS, (size_t)128 * KS, 0,
        nullptr, nullptr, nullptr, nullptr, 0, 0,
        p_bps, p_bpq, 128 * BB, nullptr, nullptr);
    k_bnfin<<<128, 256>>>(128 * BB, (float)BB * KS);
    // conv1 (BN0+leaky fused on B, stats epilogue)
    k_gemm_tc<<<dim3(KS / 128, 1, BB), 256>>>(
        c1w, p_c0, p_c1, 128, KS, 128,
        0, (size_t)128 * KS, (size_t)128 * KS, 0,
        p_bnm, p_bnr, bg0, bb0, 128, 1,
        p_bps, p_bpq, 128 * BB, nullptr, nullptr);
    k_bnfin<<<128, 256>>>(128 * BB, (float)BB * KS);
    // conv2 (BN1+leaky fused on B, stats + maxmin epilogues, no C store)
    k_gemm_tc<<<dim3(KS / 128, 2, BB), 256>>>(
        c2w, p_c1, nullptr, 256, KS, 128,
        0, (size_t)128 * KS, 0, 0,
        p_bnm, p_bnr, bg1, bb1, 128, 1,
        p_bps, p_bpq, 128 * BB, p_mx, p_mn);
    k_bnfin<<<256, 256>>>(128 * BB, (float)BB * KS);
    k_bn_max<<<(BB * 256 * NP + 255) / 256, 256>>>(bg2, bb2, out, out_size);
    k_wxyz<<<(BB * 3 * NP + 255) / 256, 256>>>(out, out_size);
}

// round 5
// speedup vs baseline: 3.0837x; 1.1789x over previous
#include <cuda_runtime.h>
#include <math.h>

#define BB    16
#define NN    2048
#define DD    64
#define NP    512
#define NS    32
#define SCC   67
#define KS    (NS*NP)      /* 16384 */
#define GPX_N 2304         /* 32*68 sgp/sgx | samp at 2176..2243 | zeros */
#define AGG0  2176
#define EPSBN 1e-5f
#define R2    0.04f

#define OUT_PTS   (BB*3*NP)
#define OUT_LOSS  (OUT_PTS + BB*256*NP)
#define OUT_UNIQ  (OUT_LOSS + 1)

// ---------------- scratch ----------------
__device__ float g_agg [BB*NN*68];           // row: pts(64) | xyz(3) | 0
__device__ float g_xn  [BB*NN];
__device__ int   g_idx [BB*NN*NS];
__device__ float g_h1  [BB*80*NN];           // rows 67..79 stay zero
__device__ float g_h2  [BB*NP*NN];
__device__ float g_w2p [NP*80];
__device__ float g_norm[BB*NP];
__device__ float g_losspart[BB];
__device__ int   g_amax[NP];
__device__ float g_spx [(size_t)BB*NP*GPX_N];
__device__ float g_inner[(size_t)BB*NP*NP];
__device__ float g_w0p [128*144];
__device__ float g_c0  [(size_t)BB*128*KS];
__device__ float g_c1  [(size_t)BB*128*KS];
__device__ float g_mx  [(size_t)BB*256*NP];
__device__ float g_mn  [(size_t)BB*256*NP];
__device__ float g_bnm [512];
__device__ float g_bnr [512];
__device__ float g_bnp_sum[512*2048];
__device__ float g_bnp_sq [512*2048];

// ---------------- prep: agg68 rows + xn ----------------
__global__ void k_prep(const float* __restrict__ xyz, const float* __restrict__ pts) {
    int i = blockIdx.x * blockDim.x + threadIdx.x;
    if (i >= BB * NN) return;
    int b = i / NN, n = i % NN;
    float* arow = g_agg + (size_t)i * 68;
    const float* p = pts + (size_t)b * DD * NN + n;
#pragma unroll 8
    for (int d = 0; d < DD; d++) arow[d] = p[(size_t)d * NN];
    const float* x = xyz + (size_t)b * 3 * NN + n;
    float a = x[0], c = x[NN], e = x[2 * NN];
    arow[64] = a; arow[65] = c; arow[66] = e; arow[67] = 0.f;
    g_xn[i] = fmaf(e, e, fmaf(c, c, a * a));
}

// ---------------- ball query ----------------
__global__ void k_ballquery() {
    __shared__ float sx[NN], sy[NN], sz[NN], sn[NN];
    int b = blockIdx.y;
    int t = threadIdx.x;
    for (int j = t; j < NN; j += blockDim.x) {
        const float* a = g_agg + ((size_t)b * NN + j) * 68;
        sx[j] = a[64]; sy[j] = a[65]; sz[j] = a[66];
        sn[j] = g_xn[b * NN + j];
    }
    __syncthreads();
    int n = blockIdx.x * blockDim.x + t;
    float px = sx[n], py = sy[n], pz = sz[n], pn = sn[n];
    int base = (b * NN + n) * NS;
    int cnt = 0, first = 0;
    for (int m = 0; m < NN && cnt < NS; m++) {
        float dot = fmaf(px, sx[m], fmaf(py, sy[m], pz * sz[m]));
        float d = pn + sn[m] - 2.0f * dot;
        if (!(d > R2)) {
            if (cnt == 0) first = m;
            g_idx[base + cnt] = m;
            cnt++;
        }
    }
    for (int j = cnt; j < NS; j++) g_idx[base + j] = first;
}

// ---------------- h1 = w1 @ agg  (B,80,NN; rows 67+ untouched=0) ----------------
__global__ void k_h1(const float* __restrict__ w1) {
    __shared__ float w[SCC];
    int o = blockIdx.y, b = blockIdx.z;
    if (threadIdx.x < SCC) w[threadIdx.x] = w1[o * SCC + threadIdx.x];
    __syncthreads();
    int n = blockIdx.x * blockDim.x + threadIdx.x;
    const float* arow = g_agg + ((size_t)(b * NN + n)) * 68;
    float s = 0.f;
#pragma unroll 1
    for (int c = 0; c < SCC; c++) s = fmaf(w[c], arow[c], s);
    g_h1[((size_t)b * 80 + o) * NN + n] = s;
}

// ---------------- BN stats (strided channel layout) ----------------
__global__ void k_bnstats(const float* __restrict__ x, int C, int Cs, int S) {
    int c = blockIdx.x, t = threadIdx.x;
    float s = 0.f, sq = 0.f;
    for (int b = 0; b < BB; b++) {
        const float* p = x + ((size_t)b * Cs + c) * S;
        for (int j = t; j < S; j += 256) { float v = p[j]; s += v; sq = fmaf(v, v, sq); }
    }
    __shared__ float rs[256], rq[256];
    rs[t] = s; rq[t] = sq; __syncthreads();
    for (int o = 128; o > 0; o >>= 1) {
        if (t < o) { rs[t] += rs[t + o]; rq[t] += rq[t + o]; }
        __syncthreads();
    }
    if (t == 0) {
        float cnt = (float)BB * (float)S;
        float m = rs[0] / cnt;
        float v = rq[0] / cnt - m * m;
        g_bnm[c] = m;
        g_bnr[c] = rsqrtf(fmaxf(v, 0.f) + EPSBN);
    }
}

// ---------------- reduce TC partial stats ----------------
__global__ void k_bnfin(int P, float count) {
    int c = blockIdx.x, t = threadIdx.x;
    float s = 0.f, sq = 0.f;
    const float* ps = g_bnp_sum + (size_t)c * 2048;
    const float* pq = g_bnp_sq  + (size_t)c * 2048;
    for (int j = t; j < P; j += 256) { s += ps[j]; sq += pq[j]; }
    __shared__ float rs[256], rq[256];
    rs[t] = s; rq[t] = sq; __syncthreads();
    for (int o = 128; o > 0; o >>= 1) {
        if (t < o) { rs[t] += rs[t + o]; rq[t] += rq[t + o]; }
        __syncthreads();
    }
    if (t == 0) {
        float m = rs[0] / count;
        float v = rq[0] / count - m * m;
        g_bnm[c] = m;
        g_bnr[c] = rsqrtf(fmaxf(v, 0.f) + EPSBN);
    }
}

// ---------------- tf32 TC GEMM, multi-mode B ----------------
__device__ __forceinline__ unsigned f2tf(float v) {
    unsigned r; asm("cvt.rna.tf32.f32 %0, %1;" : "=r"(r) : "f"(v)); return r;
}

// mode 0: B row-major KxN (+optional BN/leaky per K-channel)
// mode 2: spx-gather: B[n,c] = agg68[(c/68<32 ? idx[n,c/68] : n)][c%68]; c/68>32 -> 0
// mode 3: conv0-edge: B[ch,col]: s=col>>5,k=col&31; ch<68: spx_s[k*68+ch];
//         68<=ch<136: spx_s[2176+ch-68]; else 0
__device__ __forceinline__ float4 ldB(
    int mode, const float* __restrict__ Bb, const int* __restrict__ idxb,
    const float* __restrict__ aggb, int N, int row, int col,
    const float* __restrict__ bnm, const float* __restrict__ bnr,
    const float* __restrict__ bng, const float* __restrict__ bnb, int bnC, int leaky)
{
    float4 v = make_float4(0.f, 0.f, 0.f, 0.f);
    if (mode == 0) {
        v = *(const float4*)&Bb[(size_t)row * N + col];
        if (bnm) {
            if (row < bnC) {
                float m = bnm[row], s = bnr[row] * bng[row], o = bnb[row];
                v.x = (v.x - m) * s + o; v.y = (v.y - m) * s + o;
                v.z = (v.z - m) * s + o; v.w = (v.w - m) * s + o;
                if (leaky) {
                    v.x = v.x > 0.f ? v.x : 0.2f * v.x;
                    v.y = v.y > 0.f ? v.y : 0.2f * v.y;
                    v.z = v.z > 0.f ? v.z : 0.2f * v.z;
                    v.w = v.w > 0.f ? v.w : 0.2f * v.w;
                }
            } else v = make_float4(0.f, 0.f, 0.f, 0.f);
        }
    } else if (mode == 2) {
        int kk = col / 68;
        int d  = col - kk * 68;
        if (kk <= 32) {
            int id = (kk < 32) ? idxb[row * NS + kk] : row;
            v = *(const float4*)&aggb[(size_t)id * 68 + d];
        }
    } else { // mode 3
        int s = col >> 5, k = col & 31, ch = row;
        const float* sp = Bb + (size_t)s * GPX_N;
        if (ch < 68) {
            v.x = sp[(k + 0) * 68 + ch];
            v.y = sp[(k + 1) * 68 + ch];
            v.z = sp[(k + 2) * 68 + ch];
            v.w = sp[(k + 3) * 68 + ch];
        } else if (ch < 136) {
            float w = sp[AGG0 + ch - 68];
            v = make_float4(w, w, w, w);
        }
    }
    return v;
}

#define TC_LD(k0) { \
    ra0 = *(const float4*)&Ab[(size_t)(row0+ar0)*K + (k0) + ak0]; \
    ra1 = *(const float4*)&Ab[(size_t)(row0+ar1)*K + (k0) + ak1]; \
    if (bT) { \
        rb0 = *(const float4*)&Bb[(size_t)(col0+ar0)*K + (k0) + ak0]; \
        rb1 = *(const float4*)&Bb[(size_t)(col0+ar1)*K + (k0) + ak1]; \
    } else { \
        rb0 = ldB(mode, Bb, idxb, aggb, N, (k0)+br0, col0+bc0, bnm, bnr, bng, bnb, bnC, leaky); \
        rb1 = ldB(mode, Bb, idxb, aggb, N, (k0)+br1, col0+bc1, bnm, bnr, bng, bnb, bnC, leaky); \
    } }

#define TC_ST() { \
    As[ak0+0][ar0]=f2tf(ra0.x); As[ak0+1][ar0]=f2tf(ra0.y); As[ak0+2][ar0]=f2tf(ra0.z); As[ak0+3][ar0]=f2tf(ra0.w); \
    As[ak1+0][ar1]=f2tf(ra1.x); As[ak1+1][ar1]=f2tf(ra1.y); As[ak1+2][ar1]=f2tf(ra1.z); As[ak1+3][ar1]=f2tf(ra1.w); \
    if (bT) { \
        Bs[ak0+0][ar0]=f2tf(rb0.x); Bs[ak0+1][ar0]=f2tf(rb0.y); Bs[ak0+2][ar0]=f2tf(rb0.z); Bs[ak0+3][ar0]=f2tf(rb0.w); \
        Bs[ak1+0][ar1]=f2tf(rb1.x); Bs[ak1+1][ar1]=f2tf(rb1.y); Bs[ak1+2][ar1]=f2tf(rb1.z); Bs[ak1+3][ar1]=f2tf(rb1.w); \
    } else { \
        Bs[br0][bc0+0]=f2tf(rb0.x); Bs[br0][bc0+1]=f2tf(rb0.y); Bs[br0][bc0+2]=f2tf(rb0.z); Bs[br0][bc0+3]=f2tf(rb0.w); \
        Bs[br1][bc1+0]=f2tf(rb1.x); Bs[br1][bc1+1]=f2tf(rb1.y); Bs[br1][bc1+2]=f2tf(rb1.z); Bs[br1][bc1+3]=f2tf(rb1.w); \
    } }

__global__ __launch_bounds__(256, 2) void k_gemm_tc(
    const float* __restrict__ A, const float* __restrict__ B, float* __restrict__ C,
    int M, int N, int K, size_t sA, size_t sB, size_t sC,
    int mode, int bT, int tri,
    const int* __restrict__ idxg, const float* __restrict__ aggg,
    const float* __restrict__ bnm, const float* __restrict__ bnr,
    const float* __restrict__ bng, const float* __restrict__ bnb, int bnC, int leaky,
    float* __restrict__ bnp_sum, float* __restrict__ bnp_sq,
    float* __restrict__ mxp, float* __restrict__ mnp)
{
    __shared__ unsigned As[16][136];
    __shared__ unsigned Bs[16][136];
    __shared__ float ssum[8][64];
    __shared__ float ssq [8][64];
    const float* Ab = A + blockIdx.z * sA;
    const float* Bb = B + blockIdx.z * sB;
    const int*   idxb = idxg + (size_t)blockIdx.z * NN * NS;
    const float* aggb = aggg + (size_t)blockIdx.z * NN * 68;
    int t = threadIdx.x, lane = t & 31, wid = t >> 5;
    int g = lane >> 2, tid4 = lane & 3;
    int wm = (wid >> 2) * 64, wn = (wid & 3) * 32;
    int row0, col0;
    if (tri) {
        const int TI[10] = {0,0,0,0,1,1,1,2,2,3};
        const int TJ[10] = {0,1,2,3,1,2,3,2,3,3};
        row0 = TI[blockIdx.x] * 128; col0 = TJ[blockIdx.x] * 128;
    } else {
        row0 = blockIdx.y * 128; col0 = blockIdx.x * 128;
    }

    float acc[4][4][4];
#pragma unroll
    for (int i = 0; i < 4; i++)
#pragma unroll
        for (int j = 0; j < 4; j++)
#pragma unroll
            for (int r = 0; r < 4; r++) acc[i][j][r] = 0.f;

    int l0 = t, l1 = t + 256;
    int ar0 = l0 >> 2, ak0 = (l0 & 3) * 4;
    int ar1 = l1 >> 2, ak1 = (l1 & 3) * 4;
    int br0 = l0 >> 5, bc0 = (l0 & 31) * 4;
    int br1 = l1 >> 5, bc1 = (l1 & 31) * 4;

    float4 ra0, ra1, rb0, rb1;

    TC_LD(0);
    TC_ST();
    __syncthreads();

    for (int k0 = 0; k0 < K; k0 += 16) {
        int more = (k0 + 16) < K;
        if (more) TC_LD(k0 + 16);
#pragma unroll
        for (int ks = 0; ks < 16; ks += 8) {
            unsigned af[4][4], bf[4][2];
#pragma unroll
            for (int mf = 0; mf < 4; mf++) {
                int mb = wm + mf * 16 + g;
                af[mf][0] = As[ks + tid4][mb];
                af[mf][1] = As[ks + tid4][mb + 8];
                af[mf][2] = As[ks + tid4 + 4][mb];
                af[mf][3] = As[ks + tid4 + 4][mb + 8];
            }
#pragma unroll
            for (int nf = 0; nf < 4; nf++) {
                int nb = wn + nf * 8 + g;
                bf[nf][0] = Bs[ks + tid4][nb];
                bf[nf][1] = Bs[ks + tid4 + 4][nb];
            }
#pragma unroll
            for (int mf = 0; mf < 4; mf++)
#pragma unroll
                for (int nf = 0; nf < 4; nf++) {
                    asm volatile(
                        "mma.sync.aligned.m16n8k8.row.col.f32.tf32.tf32.f32 "
                        "{%0,%1,%2,%3}, {%4,%5,%6,%7}, {%8,%9}, {%0,%1,%2,%3};"
                        : "+f"(acc[mf][nf][0]), "+f"(acc[mf][nf][1]),
                          "+f"(acc[mf][nf][2]), "+f"(acc[mf][nf][3])
                        : "r"(af[mf][0]), "r"(af[mf][1]), "r"(af[mf][2]), "r"(af[mf][3]),
                          "r"(bf[nf][0]), "r"(bf[nf][1]));
                }
        }
        __syncthreads();
        if (more) { TC_ST(); __syncthreads(); }
    }

    if (C) {
        float* Cb = C + blockIdx.z * sC;
#pragma unroll
        for (int mf = 0; mf < 4; mf++) {
#pragma unroll
            for (int nf = 0; nf < 4; nf++) {
                size_t r0 = (size_t)(row0 + wm + mf * 16 + g);
                int c = col0 + wn + nf * 8 + tid4 * 2;
                *(float2*)&Cb[r0 * N + c]       = make_float2(acc[mf][nf][0], acc[mf][nf][1]);
                *(float2*)&Cb[(r0 + 8) * N + c] = make_float2(acc[mf][nf][2], acc[mf][nf][3]);
            }
        }
    }

    if (mxp) {
        int s = (col0 + wn) >> 5;
#pragma unroll
        for (int mf = 0; mf < 4; mf++) {
            float M0 = -1e30f, m0 = 1e30f, M1 = -1e30f, m1 = 1e30f;
#pragma unroll
            for (int nf = 0; nf < 4; nf++) {
                M0 = fmaxf(M0, fmaxf(acc[mf][nf][0], acc[mf][nf][1]));
                m0 = fminf(m0, fminf(acc[mf][nf][0], acc[mf][nf][1]));
                M1 = fmaxf(M1, fmaxf(acc[mf][nf][2], acc[mf][nf][3]));
                m1 = fminf(m1, fminf(acc[mf][nf][2], acc[mf][nf][3]));
            }
            M0 = fmaxf(M0, __shfl_xor_sync(~0u, M0, 1)); M0 = fmaxf(M0, __shfl_xor_sync(~0u, M0, 2));
            m0 = fminf(m0, __shfl_xor_sync(~0u, m0, 1)); m0 = fminf(m0, __shfl_xor_sync(~0u, m0, 2));
            M1 = fmaxf(M1, __shfl_xor_sync(~0u, M1, 1)); M1 = fmaxf(M1, __shfl_xor_sync(~0u, M1, 2));
            m1 = fminf(m1, __shfl_xor_sync(~0u, m1, 1)); m1 = fminf(m1, __shfl_xor_sync(~0u, m1, 2));
            if (tid4 == 0) {
                int r = row0 + wm + mf * 16 + g;
                size_t o1 = ((size_t)blockIdx.z * M + r) * (N >> 5) + s;
                size_t o2 = ((size_t)blockIdx.z * M + r + 8) * (N >> 5) + s;
                mxp[o1] = M0; mnp[o1] = m0;
                mxp[o2] = M1; mnp[o2] = m1;
            }
        }
    }

    if (bnp_sum) {
#pragma unroll
        for (int mf = 0; mf < 4; mf++) {
            float s0 = 0.f, q0 = 0.f, s1 = 0.f, q1 = 0.f;
#pragma unroll
            for (int nf = 0; nf < 4; nf++) {
                float a = acc[mf][nf][0], b = acc[mf][nf][1];
                float c = acc[mf][nf][2], d = acc[mf][nf][3];
                s0 += a + b; q0 += a * a + b * b;
                s1 += c + d; q1 += c * c + d * d;
            }
            s0 += __shfl_xor_sync(~0u, s0, 1); s0 += __shfl_xor_sync(~0u, s0, 2);
            q0 += __shfl_xor_sync(~0u, q0, 1); q0 += __shfl_xor_sync(~0u, q0, 2);
            s1 += __shfl_xor_sync(~0u, s1, 1); s1 += __shfl_xor_sync(~0u, s1, 2);
            q1 += __shfl_xor_sync(~0u, q1, 1); q1 += __shfl_xor_sync(~0u, q1, 2);
            if (tid4 == 0) {
                ssum[wid][mf * 16 + g] = s0;     ssq[wid][mf * 16 + g] = q0;
                ssum[wid][mf * 16 + g + 8] = s1; ssq[wid][mf * 16 + g + 8] = q1;
            }
        }
        __syncthreads();
        if (t < 128) {
            int half = t >> 6, lr = t & 63;
            float s = ssum[half * 4 + 0][lr] + ssum[half * 4 + 1][lr]
                    + ssum[half * 4 + 2][lr] + ssum[half * 4 + 3][lr];
            float q = ssq[half * 4 + 0][lr] + ssq[half * 4 + 1][lr]
                    + ssq[half * 4 + 2][lr] + ssq[half * 4 + 3][lr];
            int ch = row0 + t;
            int slot = (int)(blockIdx.z * gridDim.x + blockIdx.x);
            bnp_sum[(size_t)ch * 2048 + slot] = s;
            bnp_sq [(size_t)ch * 2048 + slot] = q;
        }
    }
}

// ---------------- softmax (fused BN2 affine) ----------------
__global__ void k_softmax(const float* __restrict__ g2, const float* __restrict__ b2) {
    int row = blockIdx.x;
    int s = row & (NP - 1);
    float mch = g_bnm[s], rch = g_bnr[s] * g2[s], bch = b2[s];
    float* x = g_h2 + (size_t)row * NN;
    int t = threadIdx.x;
    __shared__ float rs[256], rq[256];
    float m = -1e30f;
    for (int j = t; j < NN; j += 256) {
        float v = (x[j] - mch) * rch + bch;
        m = fmaxf(m, v);
    }
    rs[t] = m; __syncthreads();
    for (int o = 128; o > 0; o >>= 1) { if (t < o) rs[t] = fmaxf(rs[t], rs[t + o]); __syncthreads(); }
    m = rs[0]; __syncthreads();
    float ssum = 0.f, sq = 0.f;
    for (int j = t; j < NN; j += 256) {
        float v = (x[j] - mch) * rch + bch;
        float e = expf(v - m);
        x[j] = e;
        ssum += e; sq = fmaf(e, e, sq);
    }
    rs[t] = ssum; rq[t] = sq; __syncthreads();
    for (int o = 128; o > 0; o >>= 1) { if (t < o) { rs[t] += rs[t + o]; rq[t] += rq[t + o]; } __syncthreads(); }
    ssum = rs[0]; sq = rq[0];
    float inv = 1.f / ssum;
    for (int j = t; j < NN; j += 256) x[j] *= inv;
    if (t == 0) g_norm[row] = sqrtf(sq) * inv;
}

// ---------------- argmax + unique ----------------
__global__ void k_argmax() {
    int sidx = blockIdx.x;
    const float* x = g_h2 + (size_t)sidx * NN;
    int t = threadIdx.x;
    float bv = -1e30f; int bi = NN;
    for (int j = t; j < NN; j += 256) { float v = x[j]; if (v > bv) { bv = v; bi = j; } }
    __shared__ float rv[256]; __shared__ int ri[256];
    rv[t] = bv; ri[t] = bi; __syncthreads();
    for (int o = 128; o > 0; o >>= 1) {
        if (t < o) {
            if (rv[t + o] > rv[t] || (rv[t + o] == rv[t] && ri[t + o] < ri[t])) {
                rv[t] = rv[t + o]; ri[t] = ri[t + o];
            }
        }
        __syncthreads();
    }
    if (t == 0) g_amax[sidx] = ri[0];
}

__global__ void k_unique(float* __restrict__ out, int out_size) {
    __shared__ int fl[NN];
    __shared__ int rc[256];
    int t = threadIdx.x;
    for (int j = t; j < NN; j += 256) fl[j] = 0;
    __syncthreads();
    for (int s = t; s < NP; s += 256) fl[g_amax[s]] = 1;
    __syncthreads();
    int c = 0;
    for (int j = t; j < NN; j += 256) c += fl[j];
    rc[t] = c; __syncthreads();
    for (int o = 128; o > 0; o >>= 1) { if (t < o) rc[t] += rc[t + o]; __syncthreads(); }
    if (t == 0 && OUT_UNIQ < out_size) out[OUT_UNIQ] = (float)rc[0];
}

// ---------------- cos loss (upper triangle only, x2) ----------------
__global__ void k_loss() {
    int b = blockIdx.x;
    int t = threadIdx.x;
    const float* inn = g_inner + (size_t)b * NP * NP;
    const float* nrm = g_norm + b * NP;
    float s = 0.f;
    for (int i = t; i < NP * NP; i += 256) {
        int ss = i >> 9, tt = i & (NP - 1);
        if (tt <= ss) continue;
        float v = inn[i] / (nrm[ss] * nrm[tt] + 1e-10f);
        s = fmaf(2.f * v, v, s);
    }
    __shared__ float red[256];
    red[t] = s; __syncthreads();
    for (int o = 128; o > 0; o >>= 1) { if (t < o) red[t] += red[t + o]; __syncthreads(); }
    if (t == 0) g_losspart[b] = red[0];
}

__global__ void k_lossfin(float* __restrict__ out, int out_size) {
    if (threadIdx.x == 0 && OUT_LOSS < out_size) {
        float acc = 0.f;
        for (int b = 0; b < BB; b++) acc += sqrtf(g_losspart[b]);
        out[OUT_LOSS] = acc / (float)BB;
    }
}

// ---------------- weight prep ----------------
__global__ void k_w2p(const float* __restrict__ w2) {
    int i = blockIdx.x * blockDim.x + threadIdx.x;
    if (i >= NP * 80) return;
    int o = i / 80, c = i % 80;
    g_w2p[i] = (c < SCC) ? w2[o * SCC + c] : 0.f;
}

// conv0 edge-weights: ch<64: Wb; 64..66: Wd; 68..131: Wa-Wb; 132..134: Wc-Wd
__global__ void k_padw(const float* __restrict__ w) {
    int i = blockIdx.x * blockDim.x + threadIdx.x;
    if (i >= 128 * 144) return;
    int o = i / 144, ch = i % 144;
    const float* wr = w + o * 134;
    float v = 0.f;
    if (ch < 64)       v = wr[64 + ch];
    else if (ch < 67)  v = wr[131 + (ch - 64)];
    else if (ch == 67) v = 0.f;
    else if (ch < 132) { int c = ch - 68;  v = wr[c] - wr[64 + c]; }
    else if (ch < 135) { int c = ch - 132; v = wr[128 + c] - wr[131 + c]; }
    g_w0p[i] = v;
}

// ---------------- final: BN + leaky on max/min, pick true max ----------------
__global__ void k_bn_max(const float* __restrict__ g2, const float* __restrict__ b2,
                         float* __restrict__ out, int out_size) {
    int i = blockIdx.x * blockDim.x + threadIdx.x;
    if (i >= BB * 256 * NP) return;
    int o = (i / NP) % 256;
    float mch = g_bnm[o], rch = g_bnr[o] * g2[o], bch = b2[o];
    float v1 = (g_mx[i] - mch) * rch + bch;
    float v2 = (g_mn[i] - mch) * rch + bch;
    v1 = v1 > 0.f ? v1 : 0.2f * v1;
    v2 = v2 > 0.f ? v2 : 0.2f * v2;
    int oi = OUT_PTS + i;
    if (oi < out_size) out[oi] = fmaxf(v1, v2);
}

__global__ void k_wxyz(float* __restrict__ out, int out_size) {
    int i = blockIdx.x * blockDim.x + threadIdx.x;
    if (i >= BB * 3 * NP) return;
    int s = i % NP; int c = (i / NP) % 3; int b = i / (3 * NP);
    if (i < out_size) out[i] = g_spx[((size_t)b * NP + s) * GPX_N + AGG0 + 64 + c];
}

// ---------------- launch ----------------
extern "C" void kernel_launch(void* const* d_in, const int* in_sizes, int n_in,
                              void* d_out, int out_size) {
    const float* xyz   = (const float*)d_in[0];
    const float* pts   = (const float*)d_in[1];
    const float* w1_w  = (const float*)d_in[2];
    const float* bn1_g = (const float*)d_in[4];
    const float* bn1_b = (const float*)d_in[5];
    const float* w2_w  = (const float*)d_in[6];
    const float* bn2_g = (const float*)d_in[8];
    const float* bn2_b = (const float*)d_in[9];
    const float* c0w   = (const float*)d_in[10];
    const float* bg0   = (const float*)d_in[12];
    const float* bb0   = (const float*)d_in[13];
    const float* c1w   = (const float*)d_in[14];
    const float* bg1   = (const float*)d_in[16];
    const float* bb1   = (const float*)d_in[17];
    const float* c2w   = (const float*)d_in[18];
    const float* bg2   = (const float*)d_in[20];
    const float* bb2   = (const float*)d_in[21];
    float* out = (float*)d_out;

    float *p_agg, *p_h1, *p_h2, *p_w2p, *p_spx, *p_inner, *p_w0p,
          *p_c0, *p_c1, *p_mx, *p_mn, *p_bnm, *p_bnr, *p_bps, *p_bpq;
    int* p_idx;
    cudaGetSymbolAddress((void**)&p_agg,   g_agg);
    cudaGetSymbolAddress((void**)&p_idx,   g_idx);
    cudaGetSymbolAddress((void**)&p_h1,    g_h1);
    cudaGetSymbolAddress((void**)&p_h2,    g_h2);
    cudaGetSymbolAddress((void**)&p_w2p,   g_w2p);
    cudaGetSymbolAddress((void**)&p_spx,   g_spx);
    cudaGetSymbolAddress((void**)&p_inner, g_inner);
    cudaGetSymbolAddress((void**)&p_w0p,   g_w0p);
    cudaGetSymbolAddress((void**)&p_c0,    g_c0);
    cudaGetSymbolAddress((void**)&p_c1,    g_c1);
    cudaGetSymbolAddress((void**)&p_mx,    g_mx);
    cudaGetSymbolAddress((void**)&p_mn,    g_mn);
    cudaGetSymbolAddress((void**)&p_bnm,   g_bnm);
    cudaGetSymbolAddress((void**)&p_bnr,   g_bnr);
    cudaGetSymbolAddress((void**)&p_bps,   g_bnp_sum);
    cudaGetSymbolAddress((void**)&p_bpq,   g_bnp_sq);

    k_prep<<<(BB * NN + 255) / 256, 256>>>(xyz, pts);
    k_ballquery<<<dim3(NN / 256, BB), 256>>>();
    k_h1<<<dim3(NN / 256, SCC, BB), 256>>>(w1_w);
    k_bnstats<<<SCC, 256>>>(p_h1, SCC, 80, NN);
    k_w2p<<<(NP * 80 + 255) / 256, 256>>>(w2_w);
    // h2 = w2p @ bn1(h1)  (TC tf32, K=80, bnC=67 zeroes pad rows)  <- ncu slot 5
    k_gemm_tc<<<dim3(16, 4, BB), 256>>>(
        p_w2p, p_h1, p_h2, NP, NN, 80,
        0, (size_t)80 * NN, (size_t)NP * NN,
        0, 0, 0, p_idx, p_agg,
        p_bnm, p_bnr, bn1_g, bn1_b, SCC, 0,
        nullptr, nullptr, nullptr, nullptr);
    k_bnstats<<<NP, 256>>>(p_h2, NP, NP, NN);
    k_softmax<<<BB * NP, 256>>>(bn2_g, bn2_b);
    k_argmax<<<NP, 256>>>();
    k_unique<<<1, 256>>>(out, out_size);
    // inner = sel @ sel^T  (TC NT, upper-tri blocks only)
    k_gemm_tc<<<dim3(10, 1, BB), 256>>>(
        p_h2, p_h2, p_inner, NP, NP, NN,
        (size_t)NP * NN, (size_t)NP * NN, (size_t)NP * NP,
        0, 1, 1, p_idx, p_agg,
        nullptr, nullptr, nullptr, nullptr, 0, 0,
        nullptr, nullptr, nullptr, nullptr);
    k_loss<<<BB, 256>>>();
    k_lossfin<<<1, 1>>>(out, out_size);
    // spx = sel @ gather(agg)  (TC mode2: B gathered on the fly; sgp|sgx|samp)
    k_gemm_tc<<<dim3(GPX_N / 128, 4, BB), 256>>>(
        p_h2, nullptr, p_spx, NP, GPX_N, NN,
        (size_t)NP * NN, 0, (size_t)NP * GPX_N,
        2, 0, 0, p_idx, p_agg,
        nullptr, nullptr, nullptr, nullptr, 0, 0,
        nullptr, nullptr, nullptr, nullptr);
    k_padw<<<(128 * 144 + 255) / 256, 256>>>(c0w);
    // conv0  (TC mode3: edge synthesized from spx; stats epilogue)
    k_gemm_tc<<<dim3(KS / 128, 1, BB), 256>>>(
        p_w0p, p_spx, p_c0, 128, KS, 144,
        0, (size_t)NP * GPX_N, (size_t)128 * KS,
        3, 0, 0, p_idx, p_agg,
        nullptr, nullptr, nullptr, nullptr, 0, 0,
        p_bps, p_bpq, nullptr, nullptr);
    k_bnfin<<<128, 256>>>(128 * BB, (float)BB * KS);
    // conv1 (BN0+leaky fused on B, stats epilogue)
    k_gemm_tc<<<dim3(KS / 128, 1, BB), 256>>>(
        c1w, p_c0, p_c1, 128, KS, 128,
        0, (size_t)128 * KS, (size_t)128 * KS,
        0, 0, 0, p_idx, p_agg,
        p_bnm, p_bnr, bg0, bb0, 128, 1,
        p_bps, p_bpq, nullptr, nullptr);
    k_bnfin<<<128, 256>>>(128 * BB, (float)BB * KS);
    // conv2 (BN1+leaky fused on B, stats + maxmin epilogues, no C store)
    k_gemm_tc<<<dim3(KS / 128, 2, BB), 256>>>(
        c2w, p_c1, nullptr, 256, KS, 128,
        0, (size_t)128 * KS, 0,
        0, 0, 0, p_idx, p_agg,
        p_bnm, p_bnr, bg1, bb1, 128, 1,
        p_bps, p_bpq, p_mx, p_mn);
    k_bnfin<<<256, 256>>>(128 * BB, (float)BB * KS);
    k_bn_max<<<(BB * 256 * NP + 255) / 256, 256>>>(bg2, bb2, out, out_size);
    k_wxyz<<<(BB * 3 * NP + 255) / 256, 256>>>(out, out_size);
}